// round 9
// baseline (speedup 1.0000x reference)
#include <cuda_runtime.h>
#include <cuda_fp16.h>
#include <mma.h>
#include <math.h>
#include <stdint.h>

using namespace nvcuda;

#define Bb   2
#define Lseq 1024
#define Hdim 1024
#define NHn  16
#define Dd   64
#define HDd  1024          // NH * D
#define Mtot (Bb*Lseq)     // 2048

// ---------------- scratch (device globals; no allocations allowed) ----------
__device__ float g_q[Bb*Lseq*HDd];
__device__ float g_k[Bb*Lseq*HDd];
__device__ float g_v[Bb*Lseq*HDd];
__device__ float g_alpha[Bb*Lseq*NHn];
__device__ float g_beta[Bb*Lseq*NHn];
__device__ float g_y[Bb*Lseq*HDd];   // scan output, [B,NH,L,D] contiguous
__device__ float g_z[Bb*Lseq*HDd];   // after conv residual, [B,L,HD]

// ===========================================================================
// WMMA GEMM (QKV only — inputs range-safe for fp16):
// C = A @ W^T ; fp32 accuracy via in-register fp16 split:
//   A = Ah + Al ; W' = 1024*W = Wh + Wl ; D = (AhWh + AlWh + AhWl)/1024.
// CTA tile 128x128, BK=32, 256 threads = 8 warps (4m x 2n), warp tile 32x64.
// ===========================================================================
#define RSTRH 40

__global__ void __launch_bounds__(256)
gemm_wmma(const float* __restrict__ A,
          const float* __restrict__ W0f, const float* __restrict__ W1f,
          const float* __restrict__ W2f,
          float* __restrict__ C0, float* __restrict__ C1,
          float* __restrict__ C2)
{
    __shared__ __half sAh[128 * RSTRH];
    __shared__ __half sAl[128 * RSTRH];
    __shared__ __half sWh[128 * RSTRH];
    __shared__ __half sWl[128 * RSTRH];

    const int z = blockIdx.z;
    const float* Wf = (z == 0) ? W0f : (z == 1) ? W1f : W2f;
    float* C        = (z == 0) ? C0 : (z == 1) ? C1 : C2;

    const int tid = threadIdx.x;
    const int wid = tid >> 5;
    const int wm = wid & 3, wn = wid >> 2;
    const int m0 = blockIdx.y * 128, n0 = blockIdx.x * 128;

    wmma::fragment<wmma::accumulator, 16, 16, 16, float> acc[2][4];
#pragma unroll
    for (int mt = 0; mt < 2; mt++)
#pragma unroll
        for (int nt = 0; nt < 4; nt++)
            wmma::fill_fragment(acc[mt][nt], 0.0f);

    const int row = tid >> 1;          // 0..127
    const int hh  = tid & 1;           // which 16 of the 32 k
    const float* Ap = A  + (size_t)(m0 + row) * 1024 + hh * 16;
    const float* Wp = Wf + (size_t)(n0 + row) * 1024 + hh * 16;
    const uint32_t soff = (uint32_t)(row * 80 + hh * 32);   // bytes

    for (int k0 = 0; k0 < 1024; k0 += 32) {
        float av[16], wv[16];
#pragma unroll
        for (int j = 0; j < 4; j++) {
            float4 fa = *(const float4*)(Ap + k0 + j * 4);
            float4 fw = *(const float4*)(Wp + k0 + j * 4);
            av[j * 4 + 0] = fa.x; av[j * 4 + 1] = fa.y;
            av[j * 4 + 2] = fa.z; av[j * 4 + 3] = fa.w;
            wv[j * 4 + 0] = fw.x * 1024.0f; wv[j * 4 + 1] = fw.y * 1024.0f;
            wv[j * 4 + 2] = fw.z * 1024.0f; wv[j * 4 + 3] = fw.w * 1024.0f;
        }
        uint32_t ahw[8], alw[8], whw[8], wlw[8];
#pragma unroll
        for (int j = 0; j < 8; j++) {
            float x0 = av[2 * j], x1 = av[2 * j + 1];
            __half h0 = __float2half_rn(x0), h1 = __float2half_rn(x1);
            __half l0 = __float2half_rn(x0 - __half2float(h0));
            __half l1 = __float2half_rn(x1 - __half2float(h1));
            ahw[j] = (uint32_t)__half_as_ushort(h0)
                   | ((uint32_t)__half_as_ushort(h1) << 16);
            alw[j] = (uint32_t)__half_as_ushort(l0)
                   | ((uint32_t)__half_as_ushort(l1) << 16);
            float y0 = wv[2 * j], y1 = wv[2 * j + 1];
            __half g0 = __float2half_rn(y0), g1 = __float2half_rn(y1);
            __half m0h = __float2half_rn(y0 - __half2float(g0));
            __half m1h = __float2half_rn(y1 - __half2float(g1));
            whw[j] = (uint32_t)__half_as_ushort(g0)
                   | ((uint32_t)__half_as_ushort(g1) << 16);
            wlw[j] = (uint32_t)__half_as_ushort(m0h)
                   | ((uint32_t)__half_as_ushort(m1h) << 16);
        }
        __syncthreads();
        *(uint4*)((char*)sAh + soff)      = make_uint4(ahw[0], ahw[1], ahw[2], ahw[3]);
        *(uint4*)((char*)sAh + soff + 16) = make_uint4(ahw[4], ahw[5], ahw[6], ahw[7]);
        *(uint4*)((char*)sAl + soff)      = make_uint4(alw[0], alw[1], alw[2], alw[3]);
        *(uint4*)((char*)sAl + soff + 16) = make_uint4(alw[4], alw[5], alw[6], alw[7]);
        *(uint4*)((char*)sWh + soff)      = make_uint4(whw[0], whw[1], whw[2], whw[3]);
        *(uint4*)((char*)sWh + soff + 16) = make_uint4(whw[4], whw[5], whw[6], whw[7]);
        *(uint4*)((char*)sWl + soff)      = make_uint4(wlw[0], wlw[1], wlw[2], wlw[3]);
        *(uint4*)((char*)sWl + soff + 16) = make_uint4(wlw[4], wlw[5], wlw[6], wlw[7]);
        __syncthreads();

#pragma unroll
        for (int ks = 0; ks < 2; ks++) {
            wmma::fragment<wmma::matrix_a, 16, 16, 16, __half, wmma::row_major>
                fah[2], fal[2];
#pragma unroll
            for (int mt = 0; mt < 2; mt++) {
                const __half* ap = sAh + (wm * 32 + mt * 16) * RSTRH + ks * 16;
                const __half* lp = sAl + (wm * 32 + mt * 16) * RSTRH + ks * 16;
                wmma::load_matrix_sync(fah[mt], ap, RSTRH);
                wmma::load_matrix_sync(fal[mt], lp, RSTRH);
            }
#pragma unroll
            for (int nt = 0; nt < 4; nt++) {
                wmma::fragment<wmma::matrix_b, 16, 16, 16, __half,
                               wmma::col_major> fbh, fbl;
                const __half* bp = sWh + (wn * 64 + nt * 16) * RSTRH + ks * 16;
                const __half* cp = sWl + (wn * 64 + nt * 16) * RSTRH + ks * 16;
                wmma::load_matrix_sync(fbh, bp, RSTRH);
                wmma::load_matrix_sync(fbl, cp, RSTRH);
#pragma unroll
                for (int mt = 0; mt < 2; mt++) {
                    wmma::mma_sync(acc[mt][nt], fah[mt], fbh, acc[mt][nt]);
                    wmma::mma_sync(acc[mt][nt], fal[mt], fbh, acc[mt][nt]);
                    wmma::mma_sync(acc[mt][nt], fah[mt], fbl, acc[mt][nt]);
                }
            }
        }
    }

    const float S = 1.0f / 1024.0f;
#pragma unroll
    for (int mt = 0; mt < 2; mt++) {
#pragma unroll
        for (int nt = 0; nt < 4; nt++) {
#pragma unroll
            for (int e = 0; e < acc[mt][nt].num_elements; e++)
                acc[mt][nt].x[e] *= S;
            float* cp = C + (size_t)(m0 + wm * 32 + mt * 16) * 1024
                          + (n0 + wn * 64 + nt * 16);
            wmma::store_matrix_sync(cp, acc[mt][nt], 1024, wmma::mem_row_major);
        }
    }
}

// ---------------------------------------------------------------------------
// Bias add: C[m, n] += bias[n]  for three matrices (blockIdx.z selects).
// ---------------------------------------------------------------------------
__global__ __launch_bounds__(256)
void bias_kernel(float* __restrict__ C0, float* __restrict__ C1,
                 float* __restrict__ C2,
                 const float* __restrict__ b0, const float* __restrict__ b1,
                 const float* __restrict__ b2)
{
    const int z = blockIdx.z;
    float* C       = (z == 0) ? C0 : (z == 1) ? C1 : C2;
    const float* b = (z == 0) ? b0 : (z == 1) ? b1 : b2;
    int idx = blockIdx.x * 256 + threadIdx.x;
    C[idx] += b[idx & 1023];
}

// ===========================================================================
// Round-1/7 proven fp32 SIMT GEMM — output projection (z can exceed any
// fixed fp16 range; must stay fp32).  C = A @ W^T + bias.
// ===========================================================================
__global__ __launch_bounds__(256, 2)
void gemm_tn_kernel(const float* __restrict__ A,
                    const float* __restrict__ W0,
                    const float* __restrict__ b0,
                    float* __restrict__ C0)
{
    const int Nk = 1024, Kk = 1024;
    const float* W = W0;  const float* bias = b0;  float* C = C0;

    __shared__ float As[8][132];
    __shared__ float Bs[8][132];

    const int tid = threadIdx.x;
    const int bx = blockIdx.x, by = blockIdx.y;
    const float* Ab = A + (size_t)by * 128 * Kk;
    const float* Wb = W + (size_t)bx * 128 * Kk;
    float*       Cb = C + (size_t)by * 128 * Nk + bx * 128;

    const int tx = tid & 15, ty = tid >> 4;
    const int lr = tid >> 1;
    const int lc = (tid & 1) << 2;

    float acc[8][8];
#pragma unroll
    for (int i = 0; i < 8; i++)
#pragma unroll
        for (int j = 0; j < 8; j++) acc[i][j] = 0.f;

    for (int k0 = 0; k0 < Kk; k0 += 8) {
        float4 av = *(const float4*)(Ab + (size_t)lr * Kk + k0 + lc);
        float4 wv = *(const float4*)(Wb + (size_t)lr * Kk + k0 + lc);
        __syncthreads();
        As[lc + 0][lr] = av.x; As[lc + 1][lr] = av.y;
        As[lc + 2][lr] = av.z; As[lc + 3][lr] = av.w;
        Bs[lc + 0][lr] = wv.x; Bs[lc + 1][lr] = wv.y;
        Bs[lc + 2][lr] = wv.z; Bs[lc + 3][lr] = wv.w;
        __syncthreads();
#pragma unroll
        for (int kk = 0; kk < 8; kk++) {
            float rm[8], rn[8];
#pragma unroll
            for (int i = 0; i < 8; i++) rm[i] = As[kk][ty * 8 + i];
#pragma unroll
            for (int j = 0; j < 8; j++) rn[j] = Bs[kk][tx * 8 + j];
#pragma unroll
            for (int i = 0; i < 8; i++)
#pragma unroll
                for (int j = 0; j < 8; j++)
                    acc[i][j] = fmaf(rm[i], rn[j], acc[i][j]);
        }
    }

#pragma unroll
    for (int i = 0; i < 8; i++) {
        int row = ty * 8 + i;
#pragma unroll
        for (int j4 = 0; j4 < 8; j4 += 4) {
            int col = tx * 8 + j4;
            float4 o;
            o.x = acc[i][j4 + 0] + bias[bx * 128 + col + 0];
            o.y = acc[i][j4 + 1] + bias[bx * 128 + col + 1];
            o.z = acc[i][j4 + 2] + bias[bx * 128 + col + 2];
            o.w = acc[i][j4 + 3] + bias[bx * 128 + col + 3];
            *(float4*)(Cb + (size_t)row * Nk + col) = o;
        }
    }
}

// ---------------------------------------------------------------------------
// alpha = sigmoid(X @ Wa^T), beta = softplus(X @ Wb^T).   (proven)
// ---------------------------------------------------------------------------
__global__ __launch_bounds__(256)
void ab_kernel(const float* __restrict__ X,
               const float* __restrict__ Wa, const float* __restrict__ Wb,
               float* __restrict__ alpha, float* __restrict__ beta)
{
    __shared__ float sW[32][65];
    __shared__ float sX[8][64];
    const int tid = threadIdx.x;
    const int r = tid >> 5, cc = tid & 31;
    const int m0 = blockIdx.x * 8;
    float acc = 0.f;

    for (int k0 = 0; k0 < 1024; k0 += 64) {
        __syncthreads();
        for (int idx = tid; idx < 32 * 64; idx += 256) {
            int row = idx >> 6, kk = idx & 63;
            const float* src = (row < 16) ? (Wa + row * 1024)
                                          : (Wb + (row - 16) * 1024);
            sW[row][kk] = src[k0 + kk];
        }
        for (int idx = tid; idx < 8 * 64; idx += 256) {
            int rr = idx >> 6, kk = idx & 63;
            sX[rr][kk] = X[(size_t)(m0 + rr) * 1024 + k0 + kk];
        }
        __syncthreads();
#pragma unroll 8
        for (int kk = 0; kk < 64; kk++)
            acc = fmaf(sX[r][kk], sW[cc][kk], acc);
    }

    int m = m0 + r;
    if (cc < 16) {
        alpha[m * NHn + cc] = 1.f / (1.f + expf(-acc));
    } else {
        float sp = (acc > 20.f) ? acc : log1pf(expf(acc));
        beta[m * NHn + (cc - 16)] = sp;
    }
}

// ---------------------------------------------------------------------------
// Gated delta recurrence, v2: one block per (b,h); 128 threads = 64 rows x
// 2 column-halves (32 state columns per thread).  One shfl per reduction.
// ---------------------------------------------------------------------------
#define SCT 32
__global__ __launch_bounds__(128)
void scan_kernel(const float* __restrict__ qb, const float* __restrict__ kb,
                 const float* __restrict__ vb, const float* __restrict__ ab,
                 const float* __restrict__ bbet, float* __restrict__ yb)
{
    const int blk = blockIdx.x;           // b*16 + h
    const int h = blk & 15, b = blk >> 4;
    const int tid = threadIdx.x;
    const int d  = tid >> 1;              // row 0..63
    const int hf = tid & 1;               // column half (32 cols)
    const int cb = hf * 32;

    float S[32];
#pragma unroll
    for (int j = 0; j < 32; j++) S[j] = 0.f;

    __shared__ __align__(16) float sk[SCT][64];
    __shared__ __align__(16) float sq[SCT][64];
    __shared__ __align__(16) float sv[SCT][64];
    __shared__ float sa[SCT];
    __shared__ float sbv[SCT];

    const size_t base   = (size_t)b * Lseq * HDd + h * 64;
    const size_t baseab = (size_t)b * Lseq * NHn + h;
    float* yout = yb + ((size_t)(b * NHn + h) * Lseq) * Dd;

    for (int t0 = 0; t0 < Lseq; t0 += SCT) {
        __syncthreads();
#pragma unroll
        for (int it = 0; it < 4; it++) {
            int idx = tid + it * 128;           // 0..511 float4 slots
            int t = idx >> 4, e = (idx & 15) * 4;
            size_t g = base + (size_t)(t0 + t) * HDd + e;
            *(float4*)&sk[t][e] = *(const float4*)(kb + g);
            *(float4*)&sq[t][e] = *(const float4*)(qb + g);
            *(float4*)&sv[t][e] = *(const float4*)(vb + g);
        }
        if (tid < SCT)
            sa[tid] = ab[baseab + (size_t)(t0 + tid) * NHn];
        else if (tid < 2 * SCT)
            sbv[tid - SCT] = bbet[baseab + (size_t)(t0 + tid - SCT) * NHn];
        __syncthreads();

        for (int t = 0; t < SCT; t++) {
            float kr[32], qr[32];
#pragma unroll
            for (int j = 0; j < 8; j++) {
                float4 kf = *(float4*)&sk[t][cb + j * 4];
                kr[j * 4 + 0] = kf.x; kr[j * 4 + 1] = kf.y;
                kr[j * 4 + 2] = kf.z; kr[j * 4 + 3] = kf.w;
                float4 qf = *(float4*)&sq[t][cb + j * 4];
                qr[j * 4 + 0] = qf.x; qr[j * 4 + 1] = qf.y;
                qr[j * 4 + 2] = qf.z; qr[j * 4 + 3] = qf.w;
            }
            float u0 = 0.f, u1 = 0.f, u2 = 0.f, u3 = 0.f;
#pragma unroll
            for (int j = 0; j < 32; j += 4) {
                u0 = fmaf(S[j + 0], kr[j + 0], u0);
                u1 = fmaf(S[j + 1], kr[j + 1], u1);
                u2 = fmaf(S[j + 2], kr[j + 2], u2);
                u3 = fmaf(S[j + 3], kr[j + 3], u3);
            }
            float u = (u0 + u1) + (u2 + u3);
            u += __shfl_xor_sync(0xFFFFFFFFu, u, 1);

            const float a  = sa[t];
            const float bt = sbv[t];
            const float vv = sv[t][d];
            const float w  = bt * (vv - a * u);

            float o0 = 0.f, o1 = 0.f, o2 = 0.f, o3 = 0.f;
#pragma unroll
            for (int j = 0; j < 32; j += 4) {
                S[j + 0] = fmaf(a, S[j + 0], w * kr[j + 0]);
                S[j + 1] = fmaf(a, S[j + 1], w * kr[j + 1]);
                S[j + 2] = fmaf(a, S[j + 2], w * kr[j + 2]);
                S[j + 3] = fmaf(a, S[j + 3], w * kr[j + 3]);
                o0 = fmaf(S[j + 0], qr[j + 0], o0);
                o1 = fmaf(S[j + 1], qr[j + 1], o1);
                o2 = fmaf(S[j + 2], qr[j + 2], o2);
                o3 = fmaf(S[j + 3], qr[j + 3], o3);
            }
            float o = (o0 + o1) + (o2 + o3);
            o += __shfl_xor_sync(0xFFFFFFFFu, o, 1);
            if (hf == 0)
                yout[(size_t)(t0 + t) * Dd + d] = o;
        }
    }
}

// ---------------------------------------------------------------------------
// Residual depthwise causal conv (proven, fp32 out).
// ---------------------------------------------------------------------------
__global__ __launch_bounds__(256)
void conv_kernel(const float* __restrict__ y, const float* __restrict__ Wc,
                 float* __restrict__ z)
{
    int idx = blockIdx.x * 256 + threadIdx.x;
    int cch = idx & (HDd - 1);
    int l   = (idx >> 10) & (Lseq - 1);
    float4 w = *(const float4*)(Wc + cch * 4);
    float acc = y[idx];
    if (l >= 3) acc = fmaf(w.x, y[idx - 3 * HDd], acc);
    if (l >= 2) acc = fmaf(w.y, y[idx - 2 * HDd], acc);
    if (l >= 1) acc = fmaf(w.z, y[idx - 1 * HDd], acc);
    acc = fmaf(w.w, y[idx], acc);
    z[idx] = acc;
}

// ---------------------------------------------------------------------------
extern "C" void kernel_launch(void* const* d_in, const int* in_sizes, int n_in,
                              void* d_out, int out_size)
{
    const float* hs = (const float*)d_in[0];
    const float* Wq = (const float*)d_in[1];
    const float* bq = (const float*)d_in[2];
    const float* Wk = (const float*)d_in[3];
    const float* bk = (const float*)d_in[4];
    const float* Wv = (const float*)d_in[5];
    const float* bv = (const float*)d_in[6];
    const float* Wa = (const float*)d_in[7];
    const float* Wb = (const float*)d_in[8];
    const float* Wc = (const float*)d_in[9];
    const float* Wo = (const float*)d_in[10];
    const float* bo = (const float*)d_in[11];
    float* out = (float*)d_out;

    float *pq, *pk, *pv, *pa, *pb, *py, *pz;
    cudaGetSymbolAddress((void**)&pq, g_q);
    cudaGetSymbolAddress((void**)&pk, g_k);
    cudaGetSymbolAddress((void**)&pv, g_v);
    cudaGetSymbolAddress((void**)&pa, g_alpha);
    cudaGetSymbolAddress((void**)&pb, g_beta);
    cudaGetSymbolAddress((void**)&py, g_y);
    cudaGetSymbolAddress((void**)&pz, g_z);

    // 1) fused QKV projections (tensor cores, fp16-split — range-safe inputs)
    dim3 gqkv(8, 16, 3);
    gemm_wmma<<<gqkv, 256>>>(hs, Wq, Wk, Wv, pq, pk, pv);
    dim3 gb(Mtot * 1024 / 256, 1, 3);
    bias_kernel<<<gb, 256>>>(pq, pk, pv, bq, bk, bv);

    // 2) alpha / beta gates
    ab_kernel<<<Mtot / 8, 256>>>(hs, Wa, Wb, pa, pb);

    // 3) sequential gated-delta scan (v2: 1-shfl reductions)
    scan_kernel<<<Bb * NHn, 128>>>(pq, pk, pv, pa, pb, py);

    // 4) residual depthwise causal conv (fp32)
    conv_kernel<<<(Bb * Lseq * HDd) / 256, 256>>>(py, Wc, pz);

    // 5) output projection — fp32 SIMT (z magnitude unbounded; fp16 unsafe)
    dim3 gout(8, 16, 1);
    gemm_tn_kernel<<<gout, 256>>>(pz, Wo, bo, out);
}

// round 10
// speedup vs baseline: 1.4222x; 1.4222x over previous
#include <cuda_runtime.h>
#include <cuda_fp16.h>
#include <mma.h>
#include <math.h>
#include <stdint.h>

using namespace nvcuda;

#define Bb   2
#define Lseq 1024
#define Hdim 1024
#define NHn  16
#define Dd   64
#define HDd  1024          // NH * D
#define Mtot (Bb*Lseq)     // 2048

// ---------------- scratch (device globals; no allocations allowed) ----------
__device__ float g_q[Bb*Lseq*HDd];
__device__ float g_k[Bb*Lseq*HDd];
__device__ float g_v[Bb*Lseq*HDd];
__device__ float g_alpha[Bb*Lseq*NHn];
__device__ float g_beta[Bb*Lseq*NHn];
__device__ float g_y[Bb*Lseq*HDd];   // scan output, [B,NH,L,D] contiguous
__device__ float g_z[Bb*Lseq*HDd];   // after conv residual, [B,L,HD]
__device__ float g_s[Mtot];          // per-row max |z|
__device__ float g_is[Mtot];         // 1 / g_s

// ===========================================================================
// WMMA GEMM (QKV — inputs range-safe for fp16).  Proven in rounds 7/9.
// C = A @ W^T ; A = Ah+Al ; W' = 1024W = Wh+Wl ; D = (AhWh+AlWh+AhWl)/1024.
// CTA tile 128x128, BK=32, 256 threads = 8 warps (4m x 2n), warp tile 32x64.
// ===========================================================================
#define RSTRH 40

__global__ void __launch_bounds__(256)
gemm_wmma(const float* __restrict__ A,
          const float* __restrict__ W0f, const float* __restrict__ W1f,
          const float* __restrict__ W2f,
          float* __restrict__ C0, float* __restrict__ C1,
          float* __restrict__ C2)
{
    __shared__ __half sAh[128 * RSTRH];
    __shared__ __half sAl[128 * RSTRH];
    __shared__ __half sWh[128 * RSTRH];
    __shared__ __half sWl[128 * RSTRH];

    const int z = blockIdx.z;
    const float* Wf = (z == 0) ? W0f : (z == 1) ? W1f : W2f;
    float* C        = (z == 0) ? C0 : (z == 1) ? C1 : C2;

    const int tid = threadIdx.x;
    const int wid = tid >> 5;
    const int wm = wid & 3, wn = wid >> 2;
    const int m0 = blockIdx.y * 128, n0 = blockIdx.x * 128;

    wmma::fragment<wmma::accumulator, 16, 16, 16, float> acc[2][4];
#pragma unroll
    for (int mt = 0; mt < 2; mt++)
#pragma unroll
        for (int nt = 0; nt < 4; nt++)
            wmma::fill_fragment(acc[mt][nt], 0.0f);

    const int row = tid >> 1;
    const int hh  = tid & 1;
    const float* Ap = A  + (size_t)(m0 + row) * 1024 + hh * 16;
    const float* Wp = Wf + (size_t)(n0 + row) * 1024 + hh * 16;
    const uint32_t soff = (uint32_t)(row * 80 + hh * 32);

    for (int k0 = 0; k0 < 1024; k0 += 32) {
        float av[16], wv[16];
#pragma unroll
        for (int j = 0; j < 4; j++) {
            float4 fa = *(const float4*)(Ap + k0 + j * 4);
            float4 fw = *(const float4*)(Wp + k0 + j * 4);
            av[j * 4 + 0] = fa.x; av[j * 4 + 1] = fa.y;
            av[j * 4 + 2] = fa.z; av[j * 4 + 3] = fa.w;
            wv[j * 4 + 0] = fw.x * 1024.0f; wv[j * 4 + 1] = fw.y * 1024.0f;
            wv[j * 4 + 2] = fw.z * 1024.0f; wv[j * 4 + 3] = fw.w * 1024.0f;
        }
        uint32_t ahw[8], alw[8], whw[8], wlw[8];
#pragma unroll
        for (int j = 0; j < 8; j++) {
            float x0 = av[2 * j], x1 = av[2 * j + 1];
            __half h0 = __float2half_rn(x0), h1 = __float2half_rn(x1);
            __half l0 = __float2half_rn(x0 - __half2float(h0));
            __half l1 = __float2half_rn(x1 - __half2float(h1));
            ahw[j] = (uint32_t)__half_as_ushort(h0)
                   | ((uint32_t)__half_as_ushort(h1) << 16);
            alw[j] = (uint32_t)__half_as_ushort(l0)
                   | ((uint32_t)__half_as_ushort(l1) << 16);
            float y0 = wv[2 * j], y1 = wv[2 * j + 1];
            __half g0 = __float2half_rn(y0), g1 = __float2half_rn(y1);
            __half m0h = __float2half_rn(y0 - __half2float(g0));
            __half m1h = __float2half_rn(y1 - __half2float(g1));
            whw[j] = (uint32_t)__half_as_ushort(g0)
                   | ((uint32_t)__half_as_ushort(g1) << 16);
            wlw[j] = (uint32_t)__half_as_ushort(m0h)
                   | ((uint32_t)__half_as_ushort(m1h) << 16);
        }
        __syncthreads();
        *(uint4*)((char*)sAh + soff)      = make_uint4(ahw[0], ahw[1], ahw[2], ahw[3]);
        *(uint4*)((char*)sAh + soff + 16) = make_uint4(ahw[4], ahw[5], ahw[6], ahw[7]);
        *(uint4*)((char*)sAl + soff)      = make_uint4(alw[0], alw[1], alw[2], alw[3]);
        *(uint4*)((char*)sAl + soff + 16) = make_uint4(alw[4], alw[5], alw[6], alw[7]);
        *(uint4*)((char*)sWh + soff)      = make_uint4(whw[0], whw[1], whw[2], whw[3]);
        *(uint4*)((char*)sWh + soff + 16) = make_uint4(whw[4], whw[5], whw[6], whw[7]);
        *(uint4*)((char*)sWl + soff)      = make_uint4(wlw[0], wlw[1], wlw[2], wlw[3]);
        *(uint4*)((char*)sWl + soff + 16) = make_uint4(wlw[4], wlw[5], wlw[6], wlw[7]);
        __syncthreads();

#pragma unroll
        for (int ks = 0; ks < 2; ks++) {
            wmma::fragment<wmma::matrix_a, 16, 16, 16, __half, wmma::row_major>
                fah[2], fal[2];
#pragma unroll
            for (int mt = 0; mt < 2; mt++) {
                const __half* ap = sAh + (wm * 32 + mt * 16) * RSTRH + ks * 16;
                const __half* lp = sAl + (wm * 32 + mt * 16) * RSTRH + ks * 16;
                wmma::load_matrix_sync(fah[mt], ap, RSTRH);
                wmma::load_matrix_sync(fal[mt], lp, RSTRH);
            }
#pragma unroll
            for (int nt = 0; nt < 4; nt++) {
                wmma::fragment<wmma::matrix_b, 16, 16, 16, __half,
                               wmma::col_major> fbh, fbl;
                const __half* bp = sWh + (wn * 64 + nt * 16) * RSTRH + ks * 16;
                const __half* cp = sWl + (wn * 64 + nt * 16) * RSTRH + ks * 16;
                wmma::load_matrix_sync(fbh, bp, RSTRH);
                wmma::load_matrix_sync(fbl, cp, RSTRH);
#pragma unroll
                for (int mt = 0; mt < 2; mt++) {
                    wmma::mma_sync(acc[mt][nt], fah[mt], fbh, acc[mt][nt]);
                    wmma::mma_sync(acc[mt][nt], fal[mt], fbh, acc[mt][nt]);
                    wmma::mma_sync(acc[mt][nt], fah[mt], fbl, acc[mt][nt]);
                }
            }
        }
    }

    const float S = 1.0f / 1024.0f;
#pragma unroll
    for (int mt = 0; mt < 2; mt++) {
#pragma unroll
        for (int nt = 0; nt < 4; nt++) {
#pragma unroll
            for (int e = 0; e < acc[mt][nt].num_elements; e++)
                acc[mt][nt].x[e] *= S;
            float* cp = C + (size_t)(m0 + wm * 32 + mt * 16) * 1024
                          + (n0 + wn * 64 + nt * 16);
            wmma::store_matrix_sync(cp, acc[mt][nt], 1024, wmma::mem_row_major);
        }
    }
}

// ===========================================================================
// WMMA GEMM with per-row input scaling (output projection).
// A rows pre-scaled by inv_s[m] (so |A'| <= 1: fp16-safe for ANY z range);
// stores RAW accumulator; bias_scale_kernel applies s[m]/1024 + bias later.
// ===========================================================================
__global__ void __launch_bounds__(256)
gemm_wmma_rs(const float* __restrict__ A, const float* __restrict__ Wf,
             float* __restrict__ C, const float* __restrict__ inv_s)
{
    __shared__ __half sAh[128 * RSTRH];
    __shared__ __half sAl[128 * RSTRH];
    __shared__ __half sWh[128 * RSTRH];
    __shared__ __half sWl[128 * RSTRH];

    const int tid = threadIdx.x;
    const int wid = tid >> 5;
    const int wm = wid & 3, wn = wid >> 2;
    const int m0 = blockIdx.y * 128, n0 = blockIdx.x * 128;

    wmma::fragment<wmma::accumulator, 16, 16, 16, float> acc[2][4];
#pragma unroll
    for (int mt = 0; mt < 2; mt++)
#pragma unroll
        for (int nt = 0; nt < 4; nt++)
            wmma::fill_fragment(acc[mt][nt], 0.0f);

    const int row = tid >> 1;
    const int hh  = tid & 1;
    const float isr = inv_s[m0 + row];
    const float* Ap = A  + (size_t)(m0 + row) * 1024 + hh * 16;
    const float* Wp = Wf + (size_t)(n0 + row) * 1024 + hh * 16;
    const uint32_t soff = (uint32_t)(row * 80 + hh * 32);

    for (int k0 = 0; k0 < 1024; k0 += 32) {
        float av[16], wv[16];
#pragma unroll
        for (int j = 0; j < 4; j++) {
            float4 fa = *(const float4*)(Ap + k0 + j * 4);
            float4 fw = *(const float4*)(Wp + k0 + j * 4);
            av[j * 4 + 0] = fa.x * isr; av[j * 4 + 1] = fa.y * isr;
            av[j * 4 + 2] = fa.z * isr; av[j * 4 + 3] = fa.w * isr;
            wv[j * 4 + 0] = fw.x * 1024.0f; wv[j * 4 + 1] = fw.y * 1024.0f;
            wv[j * 4 + 2] = fw.z * 1024.0f; wv[j * 4 + 3] = fw.w * 1024.0f;
        }
        uint32_t ahw[8], alw[8], whw[8], wlw[8];
#pragma unroll
        for (int j = 0; j < 8; j++) {
            float x0 = av[2 * j], x1 = av[2 * j + 1];
            __half h0 = __float2half_rn(x0), h1 = __float2half_rn(x1);
            __half l0 = __float2half_rn(x0 - __half2float(h0));
            __half l1 = __float2half_rn(x1 - __half2float(h1));
            ahw[j] = (uint32_t)__half_as_ushort(h0)
                   | ((uint32_t)__half_as_ushort(h1) << 16);
            alw[j] = (uint32_t)__half_as_ushort(l0)
                   | ((uint32_t)__half_as_ushort(l1) << 16);
            float y0 = wv[2 * j], y1 = wv[2 * j + 1];
            __half g0 = __float2half_rn(y0), g1 = __float2half_rn(y1);
            __half m0h = __float2half_rn(y0 - __half2float(g0));
            __half m1h = __float2half_rn(y1 - __half2float(g1));
            whw[j] = (uint32_t)__half_as_ushort(g0)
                   | ((uint32_t)__half_as_ushort(g1) << 16);
            wlw[j] = (uint32_t)__half_as_ushort(m0h)
                   | ((uint32_t)__half_as_ushort(m1h) << 16);
        }
        __syncthreads();
        *(uint4*)((char*)sAh + soff)      = make_uint4(ahw[0], ahw[1], ahw[2], ahw[3]);
        *(uint4*)((char*)sAh + soff + 16) = make_uint4(ahw[4], ahw[5], ahw[6], ahw[7]);
        *(uint4*)((char*)sAl + soff)      = make_uint4(alw[0], alw[1], alw[2], alw[3]);
        *(uint4*)((char*)sAl + soff + 16) = make_uint4(alw[4], alw[5], alw[6], alw[7]);
        *(uint4*)((char*)sWh + soff)      = make_uint4(whw[0], whw[1], whw[2], whw[3]);
        *(uint4*)((char*)sWh + soff + 16) = make_uint4(whw[4], whw[5], whw[6], whw[7]);
        *(uint4*)((char*)sWl + soff)      = make_uint4(wlw[0], wlw[1], wlw[2], wlw[3]);
        *(uint4*)((char*)sWl + soff + 16) = make_uint4(wlw[4], wlw[5], wlw[6], wlw[7]);
        __syncthreads();

#pragma unroll
        for (int ks = 0; ks < 2; ks++) {
            wmma::fragment<wmma::matrix_a, 16, 16, 16, __half, wmma::row_major>
                fah[2], fal[2];
#pragma unroll
            for (int mt = 0; mt < 2; mt++) {
                const __half* ap = sAh + (wm * 32 + mt * 16) * RSTRH + ks * 16;
                const __half* lp = sAl + (wm * 32 + mt * 16) * RSTRH + ks * 16;
                wmma::load_matrix_sync(fah[mt], ap, RSTRH);
                wmma::load_matrix_sync(fal[mt], lp, RSTRH);
            }
#pragma unroll
            for (int nt = 0; nt < 4; nt++) {
                wmma::fragment<wmma::matrix_b, 16, 16, 16, __half,
                               wmma::col_major> fbh, fbl;
                const __half* bp = sWh + (wn * 64 + nt * 16) * RSTRH + ks * 16;
                const __half* cp = sWl + (wn * 64 + nt * 16) * RSTRH + ks * 16;
                wmma::load_matrix_sync(fbh, bp, RSTRH);
                wmma::load_matrix_sync(fbl, cp, RSTRH);
#pragma unroll
                for (int mt = 0; mt < 2; mt++) {
                    wmma::mma_sync(acc[mt][nt], fah[mt], fbh, acc[mt][nt]);
                    wmma::mma_sync(acc[mt][nt], fal[mt], fbh, acc[mt][nt]);
                    wmma::mma_sync(acc[mt][nt], fah[mt], fbl, acc[mt][nt]);
                }
            }
        }
    }

#pragma unroll
    for (int mt = 0; mt < 2; mt++) {
#pragma unroll
        for (int nt = 0; nt < 4; nt++) {
            float* cp = C + (size_t)(m0 + wm * 32 + mt * 16) * 1024
                          + (n0 + wn * 64 + nt * 16);
            wmma::store_matrix_sync(cp, acc[mt][nt], 1024, wmma::mem_row_major);
        }
    }
}

// ---------------------------------------------------------------------------
// Per-row max |z| and reciprocal.
// ---------------------------------------------------------------------------
__global__ __launch_bounds__(256)
void rowmax_kernel(const float* __restrict__ z,
                   float* __restrict__ s, float* __restrict__ is)
{
    int m = blockIdx.x * 8 + (threadIdx.x >> 5);
    int lane = threadIdx.x & 31;
    const float* row = z + (size_t)m * 1024;
    float mx = 0.f;
    for (int j = lane; j < 1024; j += 32) mx = fmaxf(mx, fabsf(row[j]));
#pragma unroll
    for (int o = 16; o; o >>= 1)
        mx = fmaxf(mx, __shfl_xor_sync(0xFFFFFFFFu, mx, o));
    if (lane == 0) {
        mx = fmaxf(mx, 1e-30f);
        s[m] = mx;
        is[m] = 1.0f / mx;
    }
}

// ---------------------------------------------------------------------------
// Bias add (QKV): C[m, n] += bias[n].
// ---------------------------------------------------------------------------
__global__ __launch_bounds__(256)
void bias_kernel(float* __restrict__ C0, float* __restrict__ C1,
                 float* __restrict__ C2,
                 const float* __restrict__ b0, const float* __restrict__ b1,
                 const float* __restrict__ b2)
{
    const int z = blockIdx.z;
    float* C       = (z == 0) ? C0 : (z == 1) ? C1 : C2;
    const float* b = (z == 0) ? b0 : (z == 1) ? b1 : b2;
    int idx = blockIdx.x * 256 + threadIdx.x;
    C[idx] += b[idx & 1023];
}

// Bias + per-row rescale (out-proj): out = C*(s[m]/1024) + bias[n].
__global__ __launch_bounds__(256)
void bias_scale_kernel(float* __restrict__ C, const float* __restrict__ s,
                       const float* __restrict__ bias)
{
    int idx = blockIdx.x * 256 + threadIdx.x;
    int m = idx >> 10, n = idx & 1023;
    C[idx] = C[idx] * (s[m] * (1.0f / 1024.0f)) + bias[n];
}

// ---------------------------------------------------------------------------
// alpha = sigmoid(X @ Wa^T), beta = softplus(X @ Wb^T).   (proven)
// ---------------------------------------------------------------------------
__global__ __launch_bounds__(256)
void ab_kernel(const float* __restrict__ X,
               const float* __restrict__ Wa, const float* __restrict__ Wb,
               float* __restrict__ alpha, float* __restrict__ beta)
{
    __shared__ float sW[32][65];
    __shared__ float sX[8][64];
    const int tid = threadIdx.x;
    const int r = tid >> 5, cc = tid & 31;
    const int m0 = blockIdx.x * 8;
    float acc = 0.f;

    for (int k0 = 0; k0 < 1024; k0 += 64) {
        __syncthreads();
        for (int idx = tid; idx < 32 * 64; idx += 256) {
            int row = idx >> 6, kk = idx & 63;
            const float* src = (row < 16) ? (Wa + row * 1024)
                                          : (Wb + (row - 16) * 1024);
            sW[row][kk] = src[k0 + kk];
        }
        for (int idx = tid; idx < 8 * 64; idx += 256) {
            int rr = idx >> 6, kk = idx & 63;
            sX[rr][kk] = X[(size_t)(m0 + rr) * 1024 + k0 + kk];
        }
        __syncthreads();
#pragma unroll 8
        for (int kk = 0; kk < 64; kk++)
            acc = fmaf(sX[r][kk], sW[cc][kk], acc);
    }

    int m = m0 + r;
    if (cc < 16) {
        alpha[m * NHn + cc] = 1.f / (1.f + expf(-acc));
    } else {
        float sp = (acc > 20.f) ? acc : log1pf(expf(acc));
        beta[m * NHn + (cc - 16)] = sp;
    }
}

// ---------------------------------------------------------------------------
// Gated delta recurrence v1c: identical per-thread math to the PROVEN v1,
// repacked as one block per (b,h) with 512 threads (64 rows x 8 chunks) so
// each SMSP holds 4 independent row-chains (latency hiding).
// ---------------------------------------------------------------------------
#define SCT 32
__global__ __launch_bounds__(512)
void scan_kernel(const float* __restrict__ qb, const float* __restrict__ kb,
                 const float* __restrict__ vb, const float* __restrict__ ab,
                 const float* __restrict__ bbet, float* __restrict__ yb)
{
    const int blk = blockIdx.x;           // b*16 + h
    const int h = blk & 15, b = blk >> 4;
    const int tid = threadIdx.x;
    const int rl = tid >> 3;              // row 0..63
    const int c  = tid & 7;               // chunk
    const int swb = c * 9;

    float S[8] = {0.f,0.f,0.f,0.f,0.f,0.f,0.f,0.f};

    __shared__ float sk[SCT][72];
    __shared__ float sq[SCT][72];
    __shared__ float sv[SCT][64];
    __shared__ float sa[SCT];
    __shared__ float sbv[SCT];

    const size_t baseqk = (size_t)b * Lseq * HDd + h * 64;
    const size_t baseab = (size_t)b * Lseq * NHn + h;
    float* yout = yb + ((size_t)(b * NHn + h) * Lseq) * Dd;

    for (int t0 = 0; t0 < Lseq; t0 += SCT) {
        __syncthreads();
        for (int idx = tid; idx < SCT * 64; idx += 512) {
            int t = idx >> 6, e = idx & 63;
            int sw = e + (e >> 3);
            size_t g = baseqk + (size_t)(t0 + t) * HDd + e;
            sk[t][sw] = kb[g];
            sq[t][sw] = qb[g];
            sv[t][e]  = vb[g];
        }
        if (tid < SCT)
            sa[tid] = ab[baseab + (size_t)(t0 + tid) * NHn];
        else if (tid < 2 * SCT)
            sbv[tid - SCT] = bbet[baseab + (size_t)(t0 + tid - SCT) * NHn];
        __syncthreads();

        for (int t = 0; t < SCT; t++) {
            float kr[8], qr[8];
#pragma unroll
            for (int i = 0; i < 8; i++) {
                kr[i] = sk[t][swb + i];
                qr[i] = sq[t][swb + i];
            }
            float u0 = 0.f, u1 = 0.f;
#pragma unroll
            for (int i = 0; i < 8; i += 2) {
                u0 = fmaf(S[i],     kr[i],     u0);
                u1 = fmaf(S[i + 1], kr[i + 1], u1);
            }
            float u = u0 + u1;
            u += __shfl_xor_sync(0xFFFFFFFFu, u, 1);
            u += __shfl_xor_sync(0xFFFFFFFFu, u, 2);
            u += __shfl_xor_sync(0xFFFFFFFFu, u, 4);

            const float a  = sa[t];
            const float bt = sbv[t];
            const float vv = sv[t][rl];
            const float w  = bt * (vv - a * u);

            float o0 = 0.f, o1 = 0.f;
#pragma unroll
            for (int i = 0; i < 8; i += 2) {
                S[i]     = fmaf(a, S[i],     w * kr[i]);
                S[i + 1] = fmaf(a, S[i + 1], w * kr[i + 1]);
                o0 = fmaf(S[i],     qr[i],     o0);
                o1 = fmaf(S[i + 1], qr[i + 1], o1);
            }
            float o = o0 + o1;
            o += __shfl_xor_sync(0xFFFFFFFFu, o, 1);
            o += __shfl_xor_sync(0xFFFFFFFFu, o, 2);
            o += __shfl_xor_sync(0xFFFFFFFFu, o, 4);
            if (c == 0)
                yout[(size_t)(t0 + t) * Dd + rl] = o;
        }
    }
}

// ---------------------------------------------------------------------------
// Residual depthwise causal conv (proven, fp32 out).
// ---------------------------------------------------------------------------
__global__ __launch_bounds__(256)
void conv_kernel(const float* __restrict__ y, const float* __restrict__ Wc,
                 float* __restrict__ z)
{
    int idx = blockIdx.x * 256 + threadIdx.x;
    int cch = idx & (HDd - 1);
    int l   = (idx >> 10) & (Lseq - 1);
    float4 w = *(const float4*)(Wc + cch * 4);
    float acc = y[idx];
    if (l >= 3) acc = fmaf(w.x, y[idx - 3 * HDd], acc);
    if (l >= 2) acc = fmaf(w.y, y[idx - 2 * HDd], acc);
    if (l >= 1) acc = fmaf(w.z, y[idx - 1 * HDd], acc);
    acc = fmaf(w.w, y[idx], acc);
    z[idx] = acc;
}

// ---------------------------------------------------------------------------
extern "C" void kernel_launch(void* const* d_in, const int* in_sizes, int n_in,
                              void* d_out, int out_size)
{
    const float* hs = (const float*)d_in[0];
    const float* Wq = (const float*)d_in[1];
    const float* bq = (const float*)d_in[2];
    const float* Wk = (const float*)d_in[3];
    const float* bk = (const float*)d_in[4];
    const float* Wv = (const float*)d_in[5];
    const float* bv = (const float*)d_in[6];
    const float* Wa = (const float*)d_in[7];
    const float* Wb = (const float*)d_in[8];
    const float* Wc = (const float*)d_in[9];
    const float* Wo = (const float*)d_in[10];
    const float* bo = (const float*)d_in[11];
    float* out = (float*)d_out;

    float *pq, *pk, *pv, *pa, *pb, *py, *pz, *ps, *pis;
    cudaGetSymbolAddress((void**)&pq, g_q);
    cudaGetSymbolAddress((void**)&pk, g_k);
    cudaGetSymbolAddress((void**)&pv, g_v);
    cudaGetSymbolAddress((void**)&pa, g_alpha);
    cudaGetSymbolAddress((void**)&pb, g_beta);
    cudaGetSymbolAddress((void**)&py, g_y);
    cudaGetSymbolAddress((void**)&pz, g_z);
    cudaGetSymbolAddress((void**)&ps, g_s);
    cudaGetSymbolAddress((void**)&pis, g_is);

    // 1) fused QKV projections (tensor cores, fp16-split)
    dim3 gqkv(8, 16, 3);
    gemm_wmma<<<gqkv, 256>>>(hs, Wq, Wk, Wv, pq, pk, pv);
    dim3 gb(Mtot * 1024 / 256, 1, 3);
    bias_kernel<<<gb, 256>>>(pq, pk, pv, bq, bk, bv);

    // 2) alpha / beta gates
    ab_kernel<<<Mtot / 8, 256>>>(hs, Wa, Wb, pa, pb);

    // 3) sequential gated-delta scan (v1 math, 512-thread blocks)
    scan_kernel<<<Bb * NHn, 512>>>(pq, pk, pv, pa, pb, py);

    // 4) residual depthwise causal conv (fp32)
    conv_kernel<<<(Bb * Lseq * HDd) / 256, 256>>>(py, Wc, pz);

    // 5) output projection: per-row dynamic scaling -> fp16-split wmma
    rowmax_kernel<<<Mtot / 8, 256>>>(pz, ps, pis);
    dim3 gout(8, 16, 1);
    gemm_wmma_rs<<<gout, 256>>>(pz, Wo, out, pis);
    bias_scale_kernel<<<Mtot * 1024 / 256, 256>>>(out, ps, bo);
}

// round 11
// speedup vs baseline: 1.4316x; 1.0066x over previous
#include <cuda_runtime.h>
#include <cuda_fp16.h>
#include <mma.h>
#include <math.h>
#include <stdint.h>

using namespace nvcuda;

#define Bb   2
#define Lseq 1024
#define Hdim 1024
#define NHn  16
#define Dd   64
#define HDd  1024          // NH * D
#define Mtot (Bb*Lseq)     // 2048

// ---------------- scratch (device globals; no allocations allowed) ----------
__device__ float g_q[Bb*Lseq*HDd];
__device__ float g_k[Bb*Lseq*HDd];
__device__ float g_v[Bb*Lseq*HDd];
__device__ float g_alpha[Bb*Lseq*NHn];
__device__ float g_beta[Bb*Lseq*NHn];
__device__ float g_y[Bb*Lseq*HDd];   // scan output, [B,NH,L,D] contiguous
__device__ float g_z[Bb*Lseq*HDd];   // after conv residual, [B,L,HD]
__device__ float g_s[Mtot];          // per-row max |z|
__device__ float g_is[Mtot];         // 1 / g_s

// ===========================================================================
// WMMA GEMM (QKV — inputs range-safe for fp16), now with register prefetch:
// next chunk's global loads are issued before the compute phase.
// C = A @ W^T ; A = Ah+Al ; W' = 1024W = Wh+Wl ; D = (AhWh+AlWh+AhWl)/1024.
// ===========================================================================
#define RSTRH 40

__global__ void __launch_bounds__(256)
gemm_wmma(const float* __restrict__ A,
          const float* __restrict__ W0f, const float* __restrict__ W1f,
          const float* __restrict__ W2f,
          float* __restrict__ C0, float* __restrict__ C1,
          float* __restrict__ C2)
{
    __shared__ __half sAh[128 * RSTRH];
    __shared__ __half sAl[128 * RSTRH];
    __shared__ __half sWh[128 * RSTRH];
    __shared__ __half sWl[128 * RSTRH];

    const int z = blockIdx.z;
    const float* Wf = (z == 0) ? W0f : (z == 1) ? W1f : W2f;
    float* C        = (z == 0) ? C0 : (z == 1) ? C1 : C2;

    const int tid = threadIdx.x;
    const int wid = tid >> 5;
    const int wm = wid & 3, wn = wid >> 2;
    const int m0 = blockIdx.y * 128, n0 = blockIdx.x * 128;

    wmma::fragment<wmma::accumulator, 16, 16, 16, float> acc[2][4];
#pragma unroll
    for (int mt = 0; mt < 2; mt++)
#pragma unroll
        for (int nt = 0; nt < 4; nt++)
            wmma::fill_fragment(acc[mt][nt], 0.0f);

    const int row = tid >> 1;
    const int hh  = tid & 1;
    const float* Ap = A  + (size_t)(m0 + row) * 1024 + hh * 16;
    const float* Wp = Wf + (size_t)(n0 + row) * 1024 + hh * 16;
    const uint32_t soff = (uint32_t)(row * 80 + hh * 32);

    float av[16], wv[16];
#pragma unroll
    for (int j = 0; j < 4; j++) {
        float4 fa = *(const float4*)(Ap + j * 4);
        float4 fw = *(const float4*)(Wp + j * 4);
        av[j * 4 + 0] = fa.x; av[j * 4 + 1] = fa.y;
        av[j * 4 + 2] = fa.z; av[j * 4 + 3] = fa.w;
        wv[j * 4 + 0] = fw.x * 1024.0f; wv[j * 4 + 1] = fw.y * 1024.0f;
        wv[j * 4 + 2] = fw.z * 1024.0f; wv[j * 4 + 3] = fw.w * 1024.0f;
    }

    for (int k0 = 0; k0 < 1024; k0 += 32) {
        uint32_t ahw[8], alw[8], whw[8], wlw[8];
#pragma unroll
        for (int j = 0; j < 8; j++) {
            float x0 = av[2 * j], x1 = av[2 * j + 1];
            __half h0 = __float2half_rn(x0), h1 = __float2half_rn(x1);
            __half l0 = __float2half_rn(x0 - __half2float(h0));
            __half l1 = __float2half_rn(x1 - __half2float(h1));
            ahw[j] = (uint32_t)__half_as_ushort(h0)
                   | ((uint32_t)__half_as_ushort(h1) << 16);
            alw[j] = (uint32_t)__half_as_ushort(l0)
                   | ((uint32_t)__half_as_ushort(l1) << 16);
            float y0 = wv[2 * j], y1 = wv[2 * j + 1];
            __half g0 = __float2half_rn(y0), g1 = __float2half_rn(y1);
            __half m0h = __float2half_rn(y0 - __half2float(g0));
            __half m1h = __float2half_rn(y1 - __half2float(g1));
            whw[j] = (uint32_t)__half_as_ushort(g0)
                   | ((uint32_t)__half_as_ushort(g1) << 16);
            wlw[j] = (uint32_t)__half_as_ushort(m0h)
                   | ((uint32_t)__half_as_ushort(m1h) << 16);
        }
        __syncthreads();
        *(uint4*)((char*)sAh + soff)      = make_uint4(ahw[0], ahw[1], ahw[2], ahw[3]);
        *(uint4*)((char*)sAh + soff + 16) = make_uint4(ahw[4], ahw[5], ahw[6], ahw[7]);
        *(uint4*)((char*)sAl + soff)      = make_uint4(alw[0], alw[1], alw[2], alw[3]);
        *(uint4*)((char*)sAl + soff + 16) = make_uint4(alw[4], alw[5], alw[6], alw[7]);
        *(uint4*)((char*)sWh + soff)      = make_uint4(whw[0], whw[1], whw[2], whw[3]);
        *(uint4*)((char*)sWh + soff + 16) = make_uint4(whw[4], whw[5], whw[6], whw[7]);
        *(uint4*)((char*)sWl + soff)      = make_uint4(wlw[0], wlw[1], wlw[2], wlw[3]);
        *(uint4*)((char*)sWl + soff + 16) = make_uint4(wlw[4], wlw[5], wlw[6], wlw[7]);
        // prefetch next chunk while this chunk computes
        if (k0 + 32 < 1024) {
#pragma unroll
            for (int j = 0; j < 4; j++) {
                float4 fa = *(const float4*)(Ap + k0 + 32 + j * 4);
                float4 fw = *(const float4*)(Wp + k0 + 32 + j * 4);
                av[j * 4 + 0] = fa.x; av[j * 4 + 1] = fa.y;
                av[j * 4 + 2] = fa.z; av[j * 4 + 3] = fa.w;
                wv[j * 4 + 0] = fw.x * 1024.0f; wv[j * 4 + 1] = fw.y * 1024.0f;
                wv[j * 4 + 2] = fw.z * 1024.0f; wv[j * 4 + 3] = fw.w * 1024.0f;
            }
        }
        __syncthreads();

#pragma unroll
        for (int ks = 0; ks < 2; ks++) {
            wmma::fragment<wmma::matrix_a, 16, 16, 16, __half, wmma::row_major>
                fah[2], fal[2];
#pragma unroll
            for (int mt = 0; mt < 2; mt++) {
                const __half* ap = sAh + (wm * 32 + mt * 16) * RSTRH + ks * 16;
                const __half* lp = sAl + (wm * 32 + mt * 16) * RSTRH + ks * 16;
                wmma::load_matrix_sync(fah[mt], ap, RSTRH);
                wmma::load_matrix_sync(fal[mt], lp, RSTRH);
            }
#pragma unroll
            for (int nt = 0; nt < 4; nt++) {
                wmma::fragment<wmma::matrix_b, 16, 16, 16, __half,
                               wmma::col_major> fbh, fbl;
                const __half* bp = sWh + (wn * 64 + nt * 16) * RSTRH + ks * 16;
                const __half* cp = sWl + (wn * 64 + nt * 16) * RSTRH + ks * 16;
                wmma::load_matrix_sync(fbh, bp, RSTRH);
                wmma::load_matrix_sync(fbl, cp, RSTRH);
#pragma unroll
                for (int mt = 0; mt < 2; mt++) {
                    wmma::mma_sync(acc[mt][nt], fah[mt], fbh, acc[mt][nt]);
                    wmma::mma_sync(acc[mt][nt], fal[mt], fbh, acc[mt][nt]);
                    wmma::mma_sync(acc[mt][nt], fah[mt], fbl, acc[mt][nt]);
                }
            }
        }
    }

    const float S = 1.0f / 1024.0f;
#pragma unroll
    for (int mt = 0; mt < 2; mt++) {
#pragma unroll
        for (int nt = 0; nt < 4; nt++) {
#pragma unroll
            for (int e = 0; e < acc[mt][nt].num_elements; e++)
                acc[mt][nt].x[e] *= S;
            float* cp = C + (size_t)(m0 + wm * 32 + mt * 16) * 1024
                          + (n0 + wn * 64 + nt * 16);
            wmma::store_matrix_sync(cp, acc[mt][nt], 1024, wmma::mem_row_major);
        }
    }
}

// ===========================================================================
// WMMA GEMM with per-row input scaling (output projection).  PROVEN round 10.
// ===========================================================================
__global__ void __launch_bounds__(256)
gemm_wmma_rs(const float* __restrict__ A, const float* __restrict__ Wf,
             float* __restrict__ C, const float* __restrict__ inv_s)
{
    __shared__ __half sAh[128 * RSTRH];
    __shared__ __half sAl[128 * RSTRH];
    __shared__ __half sWh[128 * RSTRH];
    __shared__ __half sWl[128 * RSTRH];

    const int tid = threadIdx.x;
    const int wid = tid >> 5;
    const int wm = wid & 3, wn = wid >> 2;
    const int m0 = blockIdx.y * 128, n0 = blockIdx.x * 128;

    wmma::fragment<wmma::accumulator, 16, 16, 16, float> acc[2][4];
#pragma unroll
    for (int mt = 0; mt < 2; mt++)
#pragma unroll
        for (int nt = 0; nt < 4; nt++)
            wmma::fill_fragment(acc[mt][nt], 0.0f);

    const int row = tid >> 1;
    const int hh  = tid & 1;
    const float isr = inv_s[m0 + row];
    const float* Ap = A  + (size_t)(m0 + row) * 1024 + hh * 16;
    const float* Wp = Wf + (size_t)(n0 + row) * 1024 + hh * 16;
    const uint32_t soff = (uint32_t)(row * 80 + hh * 32);

    for (int k0 = 0; k0 < 1024; k0 += 32) {
        float av[16], wv[16];
#pragma unroll
        for (int j = 0; j < 4; j++) {
            float4 fa = *(const float4*)(Ap + k0 + j * 4);
            float4 fw = *(const float4*)(Wp + k0 + j * 4);
            av[j * 4 + 0] = fa.x * isr; av[j * 4 + 1] = fa.y * isr;
            av[j * 4 + 2] = fa.z * isr; av[j * 4 + 3] = fa.w * isr;
            wv[j * 4 + 0] = fw.x * 1024.0f; wv[j * 4 + 1] = fw.y * 1024.0f;
            wv[j * 4 + 2] = fw.z * 1024.0f; wv[j * 4 + 3] = fw.w * 1024.0f;
        }
        uint32_t ahw[8], alw[8], whw[8], wlw[8];
#pragma unroll
        for (int j = 0; j < 8; j++) {
            float x0 = av[2 * j], x1 = av[2 * j + 1];
            __half h0 = __float2half_rn(x0), h1 = __float2half_rn(x1);
            __half l0 = __float2half_rn(x0 - __half2float(h0));
            __half l1 = __float2half_rn(x1 - __half2float(h1));
            ahw[j] = (uint32_t)__half_as_ushort(h0)
                   | ((uint32_t)__half_as_ushort(h1) << 16);
            alw[j] = (uint32_t)__half_as_ushort(l0)
                   | ((uint32_t)__half_as_ushort(l1) << 16);
            float y0 = wv[2 * j], y1 = wv[2 * j + 1];
            __half g0 = __float2half_rn(y0), g1 = __float2half_rn(y1);
            __half m0h = __float2half_rn(y0 - __half2float(g0));
            __half m1h = __float2half_rn(y1 - __half2float(g1));
            whw[j] = (uint32_t)__half_as_ushort(g0)
                   | ((uint32_t)__half_as_ushort(g1) << 16);
            wlw[j] = (uint32_t)__half_as_ushort(m0h)
                   | ((uint32_t)__half_as_ushort(m1h) << 16);
        }
        __syncthreads();
        *(uint4*)((char*)sAh + soff)      = make_uint4(ahw[0], ahw[1], ahw[2], ahw[3]);
        *(uint4*)((char*)sAh + soff + 16) = make_uint4(ahw[4], ahw[5], ahw[6], ahw[7]);
        *(uint4*)((char*)sAl + soff)      = make_uint4(alw[0], alw[1], alw[2], alw[3]);
        *(uint4*)((char*)sAl + soff + 16) = make_uint4(alw[4], alw[5], alw[6], alw[7]);
        *(uint4*)((char*)sWh + soff)      = make_uint4(whw[0], whw[1], whw[2], whw[3]);
        *(uint4*)((char*)sWh + soff + 16) = make_uint4(whw[4], whw[5], whw[6], whw[7]);
        *(uint4*)((char*)sWl + soff)      = make_uint4(wlw[0], wlw[1], wlw[2], wlw[3]);
        *(uint4*)((char*)sWl + soff + 16) = make_uint4(wlw[4], wlw[5], wlw[6], wlw[7]);
        __syncthreads();

#pragma unroll
        for (int ks = 0; ks < 2; ks++) {
            wmma::fragment<wmma::matrix_a, 16, 16, 16, __half, wmma::row_major>
                fah[2], fal[2];
#pragma unroll
            for (int mt = 0; mt < 2; mt++) {
                const __half* ap = sAh + (wm * 32 + mt * 16) * RSTRH + ks * 16;
                const __half* lp = sAl + (wm * 32 + mt * 16) * RSTRH + ks * 16;
                wmma::load_matrix_sync(fah[mt], ap, RSTRH);
                wmma::load_matrix_sync(fal[mt], lp, RSTRH);
            }
#pragma unroll
            for (int nt = 0; nt < 4; nt++) {
                wmma::fragment<wmma::matrix_b, 16, 16, 16, __half,
                               wmma::col_major> fbh, fbl;
                const __half* bp = sWh + (wn * 64 + nt * 16) * RSTRH + ks * 16;
                const __half* cp = sWl + (wn * 64 + nt * 16) * RSTRH + ks * 16;
                wmma::load_matrix_sync(fbh, bp, RSTRH);
                wmma::load_matrix_sync(fbl, cp, RSTRH);
#pragma unroll
                for (int mt = 0; mt < 2; mt++) {
                    wmma::mma_sync(acc[mt][nt], fah[mt], fbh, acc[mt][nt]);
                    wmma::mma_sync(acc[mt][nt], fal[mt], fbh, acc[mt][nt]);
                    wmma::mma_sync(acc[mt][nt], fah[mt], fbl, acc[mt][nt]);
                }
            }
        }
    }

#pragma unroll
    for (int mt = 0; mt < 2; mt++) {
#pragma unroll
        for (int nt = 0; nt < 4; nt++) {
            float* cp = C + (size_t)(m0 + wm * 32 + mt * 16) * 1024
                          + (n0 + wn * 64 + nt * 16);
            wmma::store_matrix_sync(cp, acc[mt][nt], 1024, wmma::mem_row_major);
        }
    }
}

// ---------------------------------------------------------------------------
// Per-row max |z| and reciprocal.   (proven)
// ---------------------------------------------------------------------------
__global__ __launch_bounds__(256)
void rowmax_kernel(const float* __restrict__ z,
                   float* __restrict__ s, float* __restrict__ is)
{
    int m = blockIdx.x * 8 + (threadIdx.x >> 5);
    int lane = threadIdx.x & 31;
    const float* row = z + (size_t)m * 1024;
    float mx = 0.f;
    for (int j = lane; j < 1024; j += 32) mx = fmaxf(mx, fabsf(row[j]));
#pragma unroll
    for (int o = 16; o; o >>= 1)
        mx = fmaxf(mx, __shfl_xor_sync(0xFFFFFFFFu, mx, o));
    if (lane == 0) {
        mx = fmaxf(mx, 1e-30f);
        s[m] = mx;
        is[m] = 1.0f / mx;
    }
}

// ---------------------------------------------------------------------------
// Bias add (QKV): C[m, n] += bias[n].   (proven)
// ---------------------------------------------------------------------------
__global__ __launch_bounds__(256)
void bias_kernel(float* __restrict__ C0, float* __restrict__ C1,
                 float* __restrict__ C2,
                 const float* __restrict__ b0, const float* __restrict__ b1,
                 const float* __restrict__ b2)
{
    const int z = blockIdx.z;
    float* C       = (z == 0) ? C0 : (z == 1) ? C1 : C2;
    const float* b = (z == 0) ? b0 : (z == 1) ? b1 : b2;
    int idx = blockIdx.x * 256 + threadIdx.x;
    C[idx] += b[idx & 1023];
}

// Bias + per-row rescale (out-proj): out = C*(s[m]/1024) + bias[n].  (proven)
__global__ __launch_bounds__(256)
void bias_scale_kernel(float* __restrict__ C, const float* __restrict__ s,
                       const float* __restrict__ bias)
{
    int idx = blockIdx.x * 256 + threadIdx.x;
    int m = idx >> 10, n = idx & 1023;
    C[idx] = C[idx] * (s[m] * (1.0f / 1024.0f)) + bias[n];
}

// ---------------------------------------------------------------------------
// alpha = sigmoid(X @ Wa^T), beta = softplus(X @ Wb^T).   (proven)
// ---------------------------------------------------------------------------
__global__ __launch_bounds__(256)
void ab_kernel(const float* __restrict__ X,
               const float* __restrict__ Wa, const float* __restrict__ Wb,
               float* __restrict__ alpha, float* __restrict__ beta)
{
    __shared__ float sW[32][65];
    __shared__ float sX[8][64];
    const int tid = threadIdx.x;
    const int r = tid >> 5, cc = tid & 31;
    const int m0 = blockIdx.x * 8;
    float acc = 0.f;

    for (int k0 = 0; k0 < 1024; k0 += 64) {
        __syncthreads();
        for (int idx = tid; idx < 32 * 64; idx += 256) {
            int row = idx >> 6, kk = idx & 63;
            const float* src = (row < 16) ? (Wa + row * 1024)
                                          : (Wb + (row - 16) * 1024);
            sW[row][kk] = src[k0 + kk];
        }
        for (int idx = tid; idx < 8 * 64; idx += 256) {
            int rr = idx >> 6, kk = idx & 63;
            sX[rr][kk] = X[(size_t)(m0 + rr) * 1024 + k0 + kk];
        }
        __syncthreads();
#pragma unroll 8
        for (int kk = 0; kk < 64; kk++)
            acc = fmaf(sX[r][kk], sW[cc][kk], acc);
    }

    int m = m0 + r;
    if (cc < 16) {
        alpha[m * NHn + cc] = 1.f / (1.f + expf(-acc));
    } else {
        float sp = (acc > 20.f) ? acc : log1pf(expf(acc));
        beta[m * NHn + (cc - 16)] = sp;
    }
}

// ---------------------------------------------------------------------------
// Gated delta recurrence v3: PROVEN v1 geometry (128 blocks x 128 thr,
// 16 rows x 8 chunks) with concurrent reductions:
//   p[t] = k_t . q_t   (precomputed per chunk from staged smem)
//   u  = S k ;  uq = S q   (independent -> shfl trees pipeline)
//   w  = beta*(v - alpha*u)
//   o  = alpha*uq + w*p    (exact identity; no post-update dot needed)
//   S  = alpha*S + w*k
// ---------------------------------------------------------------------------
#define SCAN_T 32
__global__ __launch_bounds__(128)
void scan_kernel(const float* __restrict__ qb, const float* __restrict__ kb,
                 const float* __restrict__ vb, const float* __restrict__ ab,
                 const float* __restrict__ bbet, float* __restrict__ yb)
{
    const int blk = blockIdx.x;           // b*64 + h*4 + rg
    const int rg = blk & 3;
    const int h  = (blk >> 2) & 15;
    const int b  = blk >> 6;
    const int tid = threadIdx.x;
    const int rl = tid >> 3;              // row within group 0..15
    const int c  = tid & 7;               // chunk
    const int swb = c * 9;

    float S[8] = {0.f,0.f,0.f,0.f,0.f,0.f,0.f,0.f};

    __shared__ float sk[SCAN_T][72];
    __shared__ float sq[SCAN_T][72];
    __shared__ float sv[SCAN_T][16];
    __shared__ float sa[SCAN_T];
    __shared__ float sbv[SCAN_T];
    __shared__ float sp[SCAN_T];

    const size_t baseqk = (size_t)b * Lseq * HDd + h * 64;
    const size_t basev  = baseqk + rg * 16;
    const size_t baseab = (size_t)b * Lseq * NHn + h;
    float* yout = yb + ((size_t)(b * NHn + h) * Lseq) * Dd + rg * 16;

    for (int t0 = 0; t0 < Lseq; t0 += SCAN_T) {
        __syncthreads();
        for (int idx = tid; idx < SCAN_T * 64; idx += 128) {
            int t = idx >> 6, e = idx & 63;
            int sw = e + (e >> 3);
            size_t g = baseqk + (size_t)(t0 + t) * HDd + e;
            sk[t][sw] = kb[g];
            sq[t][sw] = qb[g];
        }
        for (int idx = tid; idx < SCAN_T * 16; idx += 128) {
            int t = idx >> 4, rr = idx & 15;
            sv[t][rr] = vb[basev + (size_t)(t0 + t) * HDd + rr];
        }
        if (tid < SCAN_T)
            sa[tid] = ab[baseab + (size_t)(t0 + tid) * NHn];
        else if (tid < 2 * SCAN_T)
            sbv[tid - SCAN_T] = bbet[baseab + (size_t)(t0 + tid - SCAN_T) * NHn];
        __syncthreads();

        // p[t] = k_t . q_t  (4 lanes x 16 elems per t)
        {
            int t = tid >> 2;          // 0..31
            int part = tid & 3;        // 0..3
            float pp = 0.f;
#pragma unroll
            for (int j = 0; j < 16; j++) {
                int e = part * 16 + j;
                int sw = e + (e >> 3);
                pp = fmaf(sk[t][sw], sq[t][sw], pp);
            }
            pp += __shfl_xor_sync(0xFFFFFFFFu, pp, 1);
            pp += __shfl_xor_sync(0xFFFFFFFFu, pp, 2);
            if (part == 0) sp[t] = pp;
        }
        __syncthreads();

        for (int t = 0; t < SCAN_T; t++) {
            float kr[8], qr[8];
#pragma unroll
            for (int i = 0; i < 8; i++) {
                kr[i] = sk[t][swb + i];
                qr[i] = sq[t][swb + i];
            }
            float u0 = 0.f, u1 = 0.f, x0 = 0.f, x1 = 0.f;
#pragma unroll
            for (int i = 0; i < 8; i += 2) {
                u0 = fmaf(S[i],     kr[i],     u0);
                u1 = fmaf(S[i + 1], kr[i + 1], u1);
                x0 = fmaf(S[i],     qr[i],     x0);
                x1 = fmaf(S[i + 1], qr[i + 1], x1);
            }
            float u  = u0 + u1;
            float uq = x0 + x1;
            u  += __shfl_xor_sync(0xFFFFFFFFu, u, 1);
            uq += __shfl_xor_sync(0xFFFFFFFFu, uq, 1);
            u  += __shfl_xor_sync(0xFFFFFFFFu, u, 2);
            uq += __shfl_xor_sync(0xFFFFFFFFu, uq, 2);
            u  += __shfl_xor_sync(0xFFFFFFFFu, u, 4);
            uq += __shfl_xor_sync(0xFFFFFFFFu, uq, 4);

            const float a  = sa[t];
            const float bt = sbv[t];
            const float vv = sv[t][rl];
            const float w  = bt * (vv - a * u);

#pragma unroll
            for (int i = 0; i < 8; i += 2) {
                S[i]     = fmaf(a, S[i],     w * kr[i]);
                S[i + 1] = fmaf(a, S[i + 1], w * kr[i + 1]);
            }
            if (c == 0) {
                float o = fmaf(a, uq, w * sp[t]);
                yout[(size_t)(t0 + t) * Dd + rl] = o;
            }
        }
    }
}

// ---------------------------------------------------------------------------
// Residual depthwise causal conv (proven, fp32 out).
// ---------------------------------------------------------------------------
__global__ __launch_bounds__(256)
void conv_kernel(const float* __restrict__ y, const float* __restrict__ Wc,
                 float* __restrict__ z)
{
    int idx = blockIdx.x * 256 + threadIdx.x;
    int cch = idx & (HDd - 1);
    int l   = (idx >> 10) & (Lseq - 1);
    float4 w = *(const float4*)(Wc + cch * 4);
    float acc = y[idx];
    if (l >= 3) acc = fmaf(w.x, y[idx - 3 * HDd], acc);
    if (l >= 2) acc = fmaf(w.y, y[idx - 2 * HDd], acc);
    if (l >= 1) acc = fmaf(w.z, y[idx - 1 * HDd], acc);
    acc = fmaf(w.w, y[idx], acc);
    z[idx] = acc;
}

// ---------------------------------------------------------------------------
extern "C" void kernel_launch(void* const* d_in, const int* in_sizes, int n_in,
                              void* d_out, int out_size)
{
    const float* hs = (const float*)d_in[0];
    const float* Wq = (const float*)d_in[1];
    const float* bq = (const float*)d_in[2];
    const float* Wk = (const float*)d_in[3];
    const float* bk = (const float*)d_in[4];
    const float* Wv = (const float*)d_in[5];
    const float* bv = (const float*)d_in[6];
    const float* Wa = (const float*)d_in[7];
    const float* Wb = (const float*)d_in[8];
    const float* Wc = (const float*)d_in[9];
    const float* Wo = (const float*)d_in[10];
    const float* bo = (const float*)d_in[11];
    float* out = (float*)d_out;

    float *pq, *pk, *pv, *pa, *pb, *py, *pz, *ps, *pis;
    cudaGetSymbolAddress((void**)&pq, g_q);
    cudaGetSymbolAddress((void**)&pk, g_k);
    cudaGetSymbolAddress((void**)&pv, g_v);
    cudaGetSymbolAddress((void**)&pa, g_alpha);
    cudaGetSymbolAddress((void**)&pb, g_beta);
    cudaGetSymbolAddress((void**)&py, g_y);
    cudaGetSymbolAddress((void**)&pz, g_z);
    cudaGetSymbolAddress((void**)&ps, g_s);
    cudaGetSymbolAddress((void**)&pis, g_is);

    // 1) fused QKV projections (tensor cores, fp16-split, reg prefetch)
    dim3 gqkv(8, 16, 3);
    gemm_wmma<<<gqkv, 256>>>(hs, Wq, Wk, Wv, pq, pk, pv);
    dim3 gb(Mtot * 1024 / 256, 1, 3);
    bias_kernel<<<gb, 256>>>(pq, pk, pv, bq, bk, bv);

    // 2) alpha / beta gates
    ab_kernel<<<Mtot / 8, 256>>>(hs, Wa, Wb, pa, pb);

    // 3) sequential gated-delta scan (v3: concurrent reductions, v1 geometry)
    scan_kernel<<<Bb * NHn * 4, 128>>>(pq, pk, pv, pa, pb, py);

    // 4) residual depthwise causal conv (fp32)
    conv_kernel<<<(Bb * Lseq * HDd) / 256, 256>>>(py, Wc, pz);

    // 5) output projection: per-row dynamic scaling -> fp16-split wmma
    rowmax_kernel<<<Mtot / 8, 256>>>(pz, ps, pis);
    dim3 gout(8, 16, 1);
    gemm_wmma_rs<<<gout, 256>>>(pz, Wo, out, pis);
    bias_scale_kernel<<<Mtot * 1024 / 256, 256>>>(out, ps, bo);
}

// round 14
// speedup vs baseline: 1.8692x; 1.3057x over previous
#include <cuda_runtime.h>
#include <cuda_fp16.h>
#include <mma.h>
#include <math.h>
#include <stdint.h>

using namespace nvcuda;

#define Bb   2
#define Lseq 1024
#define Hdim 1024
#define NHn  16
#define Dd   64
#define HDd  1024          // NH * D
#define Mtot (Bb*Lseq)     // 2048

// ---------------- scratch (device globals; no allocations allowed) ----------
__device__ float g_q[Bb*Lseq*HDd];
__device__ float g_k[Bb*Lseq*HDd];
__device__ float g_v[Bb*Lseq*HDd];
__device__ float g_alpha[Bb*Lseq*NHn];
__device__ float g_beta[Bb*Lseq*NHn];
__device__ float g_y[Bb*Lseq*HDd];   // scan output, [B,NH,L,D] contiguous
__device__ float g_z[Bb*Lseq*HDd];   // after conv residual, [B,L,HD]
__device__ float g_s[Mtot];          // per-row max |z|
__device__ float g_is[Mtot];         // 1 / g_s

// ===========================================================================
// WMMA GEMM (QKV — inputs range-safe for fp16).  Round-10 PROVEN version.
// C = A @ W^T ; A = Ah+Al ; W' = 1024W = Wh+Wl ; D = (AhWh+AlWh+AhWl)/1024.
// ===========================================================================
#define RSTRH 40

__global__ void __launch_bounds__(256)
gemm_wmma(const float* __restrict__ A,
          const float* __restrict__ W0f, const float* __restrict__ W1f,
          const float* __restrict__ W2f,
          float* __restrict__ C0, float* __restrict__ C1,
          float* __restrict__ C2)
{
    __shared__ __half sAh[128 * RSTRH];
    __shared__ __half sAl[128 * RSTRH];
    __shared__ __half sWh[128 * RSTRH];
    __shared__ __half sWl[128 * RSTRH];

    const int z = blockIdx.z;
    const float* Wf = (z == 0) ? W0f : (z == 1) ? W1f : W2f;
    float* C        = (z == 0) ? C0 : (z == 1) ? C1 : C2;

    const int tid = threadIdx.x;
    const int wid = tid >> 5;
    const int wm = wid & 3, wn = wid >> 2;
    const int m0 = blockIdx.y * 128, n0 = blockIdx.x * 128;

    wmma::fragment<wmma::accumulator, 16, 16, 16, float> acc[2][4];
#pragma unroll
    for (int mt = 0; mt < 2; mt++)
#pragma unroll
        for (int nt = 0; nt < 4; nt++)
            wmma::fill_fragment(acc[mt][nt], 0.0f);

    const int row = tid >> 1;
    const int hh  = tid & 1;
    const float* Ap = A  + (size_t)(m0 + row) * 1024 + hh * 16;
    const float* Wp = Wf + (size_t)(n0 + row) * 1024 + hh * 16;
    const uint32_t soff = (uint32_t)(row * 80 + hh * 32);

    for (int k0 = 0; k0 < 1024; k0 += 32) {
        float av[16], wv[16];
#pragma unroll
        for (int j = 0; j < 4; j++) {
            float4 fa = *(const float4*)(Ap + k0 + j * 4);
            float4 fw = *(const float4*)(Wp + k0 + j * 4);
            av[j * 4 + 0] = fa.x; av[j * 4 + 1] = fa.y;
            av[j * 4 + 2] = fa.z; av[j * 4 + 3] = fa.w;
            wv[j * 4 + 0] = fw.x * 1024.0f; wv[j * 4 + 1] = fw.y * 1024.0f;
            wv[j * 4 + 2] = fw.z * 1024.0f; wv[j * 4 + 3] = fw.w * 1024.0f;
        }
        uint32_t ahw[8], alw[8], whw[8], wlw[8];
#pragma unroll
        for (int j = 0; j < 8; j++) {
            float x0 = av[2 * j], x1 = av[2 * j + 1];
            __half h0 = __float2half_rn(x0), h1 = __float2half_rn(x1);
            __half l0 = __float2half_rn(x0 - __half2float(h0));
            __half l1 = __float2half_rn(x1 - __half2float(h1));
            ahw[j] = (uint32_t)__half_as_ushort(h0)
                   | ((uint32_t)__half_as_ushort(h1) << 16);
            alw[j] = (uint32_t)__half_as_ushort(l0)
                   | ((uint32_t)__half_as_ushort(l1) << 16);
            float y0 = wv[2 * j], y1 = wv[2 * j + 1];
            __half g0 = __float2half_rn(y0), g1 = __float2half_rn(y1);
            __half m0h = __float2half_rn(y0 - __half2float(g0));
            __half m1h = __float2half_rn(y1 - __half2float(g1));
            whw[j] = (uint32_t)__half_as_ushort(g0)
                   | ((uint32_t)__half_as_ushort(g1) << 16);
            wlw[j] = (uint32_t)__half_as_ushort(m0h)
                   | ((uint32_t)__half_as_ushort(m1h) << 16);
        }
        __syncthreads();
        *(uint4*)((char*)sAh + soff)      = make_uint4(ahw[0], ahw[1], ahw[2], ahw[3]);
        *(uint4*)((char*)sAh + soff + 16) = make_uint4(ahw[4], ahw[5], ahw[6], ahw[7]);
        *(uint4*)((char*)sAl + soff)      = make_uint4(alw[0], alw[1], alw[2], alw[3]);
        *(uint4*)((char*)sAl + soff + 16) = make_uint4(alw[4], alw[5], alw[6], alw[7]);
        *(uint4*)((char*)sWh + soff)      = make_uint4(whw[0], whw[1], whw[2], whw[3]);
        *(uint4*)((char*)sWh + soff + 16) = make_uint4(whw[4], whw[5], whw[6], whw[7]);
        *(uint4*)((char*)sWl + soff)      = make_uint4(wlw[0], wlw[1], wlw[2], wlw[3]);
        *(uint4*)((char*)sWl + soff + 16) = make_uint4(wlw[4], wlw[5], wlw[6], wlw[7]);
        __syncthreads();

#pragma unroll
        for (int ks = 0; ks < 2; ks++) {
            wmma::fragment<wmma::matrix_a, 16, 16, 16, __half, wmma::row_major>
                fah[2], fal[2];
#pragma unroll
            for (int mt = 0; mt < 2; mt++) {
                const __half* ap = sAh + (wm * 32 + mt * 16) * RSTRH + ks * 16;
                const __half* lp = sAl + (wm * 32 + mt * 16) * RSTRH + ks * 16;
                wmma::load_matrix_sync(fah[mt], ap, RSTRH);
                wmma::load_matrix_sync(fal[mt], lp, RSTRH);
            }
#pragma unroll
            for (int nt = 0; nt < 4; nt++) {
                wmma::fragment<wmma::matrix_b, 16, 16, 16, __half,
                               wmma::col_major> fbh, fbl;
                const __half* bp = sWh + (wn * 64 + nt * 16) * RSTRH + ks * 16;
                const __half* cp = sWl + (wn * 64 + nt * 16) * RSTRH + ks * 16;
                wmma::load_matrix_sync(fbh, bp, RSTRH);
                wmma::load_matrix_sync(fbl, cp, RSTRH);
#pragma unroll
                for (int mt = 0; mt < 2; mt++) {
                    wmma::mma_sync(acc[mt][nt], fah[mt], fbh, acc[mt][nt]);
                    wmma::mma_sync(acc[mt][nt], fal[mt], fbh, acc[mt][nt]);
                    wmma::mma_sync(acc[mt][nt], fah[mt], fbl, acc[mt][nt]);
                }
            }
        }
    }

    const float S = 1.0f / 1024.0f;
#pragma unroll
    for (int mt = 0; mt < 2; mt++) {
#pragma unroll
        for (int nt = 0; nt < 4; nt++) {
#pragma unroll
            for (int e = 0; e < acc[mt][nt].num_elements; e++)
                acc[mt][nt].x[e] *= S;
            float* cp = C + (size_t)(m0 + wm * 32 + mt * 16) * 1024
                          + (n0 + wn * 64 + nt * 16);
            wmma::store_matrix_sync(cp, acc[mt][nt], 1024, wmma::mem_row_major);
        }
    }
}

// ===========================================================================
// WMMA GEMM with per-row input scaling (output projection).  PROVEN round 10.
// ===========================================================================
__global__ void __launch_bounds__(256)
gemm_wmma_rs(const float* __restrict__ A, const float* __restrict__ Wf,
             float* __restrict__ C, const float* __restrict__ inv_s)
{
    __shared__ __half sAh[128 * RSTRH];
    __shared__ __half sAl[128 * RSTRH];
    __shared__ __half sWh[128 * RSTRH];
    __shared__ __half sWl[128 * RSTRH];

    const int tid = threadIdx.x;
    const int wid = tid >> 5;
    const int wm = wid & 3, wn = wid >> 2;
    const int m0 = blockIdx.y * 128, n0 = blockIdx.x * 128;

    wmma::fragment<wmma::accumulator, 16, 16, 16, float> acc[2][4];
#pragma unroll
    for (int mt = 0; mt < 2; mt++)
#pragma unroll
        for (int nt = 0; nt < 4; nt++)
            wmma::fill_fragment(acc[mt][nt], 0.0f);

    const int row = tid >> 1;
    const int hh  = tid & 1;
    const float isr = inv_s[m0 + row];
    const float* Ap = A  + (size_t)(m0 + row) * 1024 + hh * 16;
    const float* Wp = Wf + (size_t)(n0 + row) * 1024 + hh * 16;
    const uint32_t soff = (uint32_t)(row * 80 + hh * 32);

    for (int k0 = 0; k0 < 1024; k0 += 32) {
        float av[16], wv[16];
#pragma unroll
        for (int j = 0; j < 4; j++) {
            float4 fa = *(const float4*)(Ap + k0 + j * 4);
            float4 fw = *(const float4*)(Wp + k0 + j * 4);
            av[j * 4 + 0] = fa.x * isr; av[j * 4 + 1] = fa.y * isr;
            av[j * 4 + 2] = fa.z * isr; av[j * 4 + 3] = fa.w * isr;
            wv[j * 4 + 0] = fw.x * 1024.0f; wv[j * 4 + 1] = fw.y * 1024.0f;
            wv[j * 4 + 2] = fw.z * 1024.0f; wv[j * 4 + 3] = fw.w * 1024.0f;
        }
        uint32_t ahw[8], alw[8], whw[8], wlw[8];
#pragma unroll
        for (int j = 0; j < 8; j++) {
            float x0 = av[2 * j], x1 = av[2 * j + 1];
            __half h0 = __float2half_rn(x0), h1 = __float2half_rn(x1);
            __half l0 = __float2half_rn(x0 - __half2float(h0));
            __half l1 = __float2half_rn(x1 - __half2float(h1));
            ahw[j] = (uint32_t)__half_as_ushort(h0)
                   | ((uint32_t)__half_as_ushort(h1) << 16);
            alw[j] = (uint32_t)__half_as_ushort(l0)
                   | ((uint32_t)__half_as_ushort(l1) << 16);
            float y0 = wv[2 * j], y1 = wv[2 * j + 1];
            __half g0 = __float2half_rn(y0), g1 = __float2half_rn(y1);
            __half m0h = __float2half_rn(y0 - __half2float(g0));
            __half m1h = __float2half_rn(y1 - __half2float(g1));
            whw[j] = (uint32_t)__half_as_ushort(g0)
                   | ((uint32_t)__half_as_ushort(g1) << 16);
            wlw[j] = (uint32_t)__half_as_ushort(m0h)
                   | ((uint32_t)__half_as_ushort(m1h) << 16);
        }
        __syncthreads();
        *(uint4*)((char*)sAh + soff)      = make_uint4(ahw[0], ahw[1], ahw[2], ahw[3]);
        *(uint4*)((char*)sAh + soff + 16) = make_uint4(ahw[4], ahw[5], ahw[6], ahw[7]);
        *(uint4*)((char*)sAl + soff)      = make_uint4(alw[0], alw[1], alw[2], alw[3]);
        *(uint4*)((char*)sAl + soff + 16) = make_uint4(alw[4], alw[5], alw[6], alw[7]);
        *(uint4*)((char*)sWh + soff)      = make_uint4(whw[0], whw[1], whw[2], whw[3]);
        *(uint4*)((char*)sWh + soff + 16) = make_uint4(whw[4], whw[5], whw[6], whw[7]);
        *(uint4*)((char*)sWl + soff)      = make_uint4(wlw[0], wlw[1], wlw[2], wlw[3]);
        *(uint4*)((char*)sWl + soff + 16) = make_uint4(wlw[4], wlw[5], wlw[6], wlw[7]);
        __syncthreads();

#pragma unroll
        for (int ks = 0; ks < 2; ks++) {
            wmma::fragment<wmma::matrix_a, 16, 16, 16, __half, wmma::row_major>
                fah[2], fal[2];
#pragma unroll
            for (int mt = 0; mt < 2; mt++) {
                const __half* ap = sAh + (wm * 32 + mt * 16) * RSTRH + ks * 16;
                const __half* lp = sAl + (wm * 32 + mt * 16) * RSTRH + ks * 16;
                wmma::load_matrix_sync(fah[mt], ap, RSTRH);
                wmma::load_matrix_sync(fal[mt], lp, RSTRH);
            }
#pragma unroll
            for (int nt = 0; nt < 4; nt++) {
                wmma::fragment<wmma::matrix_b, 16, 16, 16, __half,
                               wmma::col_major> fbh, fbl;
                const __half* bp = sWh + (wn * 64 + nt * 16) * RSTRH + ks * 16;
                const __half* cp = sWl + (wn * 64 + nt * 16) * RSTRH + ks * 16;
                wmma::load_matrix_sync(fbh, bp, RSTRH);
                wmma::load_matrix_sync(fbl, cp, RSTRH);
#pragma unroll
                for (int mt = 0; mt < 2; mt++) {
                    wmma::mma_sync(acc[mt][nt], fah[mt], fbh, acc[mt][nt]);
                    wmma::mma_sync(acc[mt][nt], fal[mt], fbh, acc[mt][nt]);
                    wmma::mma_sync(acc[mt][nt], fah[mt], fbl, acc[mt][nt]);
                }
            }
        }
    }

#pragma unroll
    for (int mt = 0; mt < 2; mt++) {
#pragma unroll
        for (int nt = 0; nt < 4; nt++) {
            float* cp = C + (size_t)(m0 + wm * 32 + mt * 16) * 1024
                          + (n0 + wn * 64 + nt * 16);
            wmma::store_matrix_sync(cp, acc[mt][nt], 1024, wmma::mem_row_major);
        }
    }
}

// ---------------------------------------------------------------------------
// Per-row max |z| and reciprocal.   (proven)
// ---------------------------------------------------------------------------
__global__ __launch_bounds__(256)
void rowmax_kernel(const float* __restrict__ z,
                   float* __restrict__ s, float* __restrict__ is)
{
    int m = blockIdx.x * 8 + (threadIdx.x >> 5);
    int lane = threadIdx.x & 31;
    const float* row = z + (size_t)m * 1024;
    float mx = 0.f;
    for (int j = lane; j < 1024; j += 32) mx = fmaxf(mx, fabsf(row[j]));
#pragma unroll
    for (int o = 16; o; o >>= 1)
        mx = fmaxf(mx, __shfl_xor_sync(0xFFFFFFFFu, mx, o));
    if (lane == 0) {
        mx = fmaxf(mx, 1e-30f);
        s[m] = mx;
        is[m] = 1.0f / mx;
    }
}

// ---------------------------------------------------------------------------
// Bias add (QKV): C[m, n] += bias[n].   (proven)
// ---------------------------------------------------------------------------
__global__ __launch_bounds__(256)
void bias_kernel(float* __restrict__ C0, float* __restrict__ C1,
                 float* __restrict__ C2,
                 const float* __restrict__ b0, const float* __restrict__ b1,
                 const float* __restrict__ b2)
{
    const int z = blockIdx.z;
    float* C       = (z == 0) ? C0 : (z == 1) ? C1 : C2;
    const float* b = (z == 0) ? b0 : (z == 1) ? b1 : b2;
    int idx = blockIdx.x * 256 + threadIdx.x;
    C[idx] += b[idx & 1023];
}

// Bias + per-row rescale (out-proj): out = C*(s[m]/1024) + bias[n].  (proven)
__global__ __launch_bounds__(256)
void bias_scale_kernel(float* __restrict__ C, const float* __restrict__ s,
                       const float* __restrict__ bias)
{
    int idx = blockIdx.x * 256 + threadIdx.x;
    int m = idx >> 10, n = idx & 1023;
    C[idx] = C[idx] * (s[m] * (1.0f / 1024.0f)) + bias[n];
}

// ---------------------------------------------------------------------------
// alpha = sigmoid(X @ Wa^T), beta = softplus(X @ Wb^T).   (proven)
// ---------------------------------------------------------------------------
__global__ __launch_bounds__(256)
void ab_kernel(const float* __restrict__ X,
               const float* __restrict__ Wa, const float* __restrict__ Wb,
               float* __restrict__ alpha, float* __restrict__ beta)
{
    __shared__ float sW[32][65];
    __shared__ float sX[8][64];
    const int tid = threadIdx.x;
    const int r = tid >> 5, cc = tid & 31;
    const int m0 = blockIdx.x * 8;
    float acc = 0.f;

    for (int k0 = 0; k0 < 1024; k0 += 64) {
        __syncthreads();
        for (int idx = tid; idx < 32 * 64; idx += 256) {
            int row = idx >> 6, kk = idx & 63;
            const float* src = (row < 16) ? (Wa + row * 1024)
                                          : (Wb + (row - 16) * 1024);
            sW[row][kk] = src[k0 + kk];
        }
        for (int idx = tid; idx < 8 * 64; idx += 256) {
            int rr = idx >> 6, kk = idx & 63;
            sX[rr][kk] = X[(size_t)(m0 + rr) * 1024 + k0 + kk];
        }
        __syncthreads();
#pragma unroll 8
        for (int kk = 0; kk < 64; kk++)
            acc = fmaf(sX[r][kk], sW[cc][kk], acc);
    }

    int m = m0 + r;
    if (cc < 16) {
        alpha[m * NHn + cc] = 1.f / (1.f + expf(-acc));
    } else {
        float sp = (acc > 20.f) ? acc : log1pf(expf(acc));
        beta[m * NHn + (cc - 16)] = sp;
    }
}

// ---------------------------------------------------------------------------
// Gated delta recurrence v4: v3 math (PROVEN) with no swizzle and all k/q
// smem reads vectorized to float4 (16 scalar LDS -> 4 LDS.128 per step).
// Bank pattern: 8 distinct float4 per warp, broadcast x4 -> conflict-free.
// ---------------------------------------------------------------------------
#define SCAN_T 32
__global__ __launch_bounds__(128)
void scan_kernel(const float* __restrict__ qb, const float* __restrict__ kb,
                 const float* __restrict__ vb, const float* __restrict__ ab,
                 const float* __restrict__ bbet, float* __restrict__ yb)
{
    const int blk = blockIdx.x;           // b*64 + h*4 + rg
    const int rg = blk & 3;
    const int h  = (blk >> 2) & 15;
    const int b  = blk >> 6;
    const int tid = threadIdx.x;
    const int rl = tid >> 3;              // row within group 0..15
    const int c  = tid & 7;               // chunk
    const int cb = c * 8;

    float S[8] = {0.f,0.f,0.f,0.f,0.f,0.f,0.f,0.f};

    __shared__ __align__(16) float sk[SCAN_T][64];
    __shared__ __align__(16) float sq[SCAN_T][64];
    __shared__ __align__(16) float sv[SCAN_T][16];
    __shared__ float sa[SCAN_T];
    __shared__ float sbv[SCAN_T];
    __shared__ float sp[SCAN_T];

    const size_t baseqk = (size_t)b * Lseq * HDd + h * 64;
    const size_t basev  = baseqk + rg * 16;
    const size_t baseab = (size_t)b * Lseq * NHn + h;
    float* yout = yb + ((size_t)(b * NHn + h) * Lseq) * Dd + rg * 16;

    for (int t0 = 0; t0 < Lseq; t0 += SCAN_T) {
        __syncthreads();
        // k/q fill: 32 x 64 floats = 512 float4 slots, vectorized
#pragma unroll
        for (int it = 0; it < 4; it++) {
            int idx = tid + it * 128;          // 0..511
            int t = idx >> 4, e = (idx & 15) * 4;
            size_t g = baseqk + (size_t)(t0 + t) * HDd + e;
            *(float4*)&sk[t][e] = *(const float4*)(kb + g);
            *(float4*)&sq[t][e] = *(const float4*)(qb + g);
        }
        // v fill: 32 x 16 floats = 128 float4 slots
        {
            int t = tid >> 2, e = (tid & 3) * 4;
            *(float4*)&sv[t][e] =
                *(const float4*)(vb + basev + (size_t)(t0 + t) * HDd + e);
        }
        if (tid < SCAN_T)
            sa[tid] = ab[baseab + (size_t)(t0 + tid) * NHn];
        else if (tid < 2 * SCAN_T)
            sbv[tid - SCAN_T] = bbet[baseab + (size_t)(t0 + tid - SCAN_T) * NHn];
        __syncthreads();

        // p[t] = k_t . q_t  (4 lanes x 16 elems per t, vectorized)
        {
            int t = tid >> 2;          // 0..31
            int part = tid & 3;        // 0..3
            float pp = 0.f;
#pragma unroll
            for (int j4 = 0; j4 < 4; j4++) {
                float4 kf = *(float4*)&sk[t][part * 16 + j4 * 4];
                float4 qf = *(float4*)&sq[t][part * 16 + j4 * 4];
                pp = fmaf(kf.x, qf.x, pp);
                pp = fmaf(kf.y, qf.y, pp);
                pp = fmaf(kf.z, qf.z, pp);
                pp = fmaf(kf.w, qf.w, pp);
            }
            pp += __shfl_xor_sync(0xFFFFFFFFu, pp, 1);
            pp += __shfl_xor_sync(0xFFFFFFFFu, pp, 2);
            if (part == 0) sp[t] = pp;
        }
        __syncthreads();

        for (int t = 0; t < SCAN_T; t++) {
            float kr[8], qr[8];
            {
                float4 k0v = *(float4*)&sk[t][cb];
                float4 k1v = *(float4*)&sk[t][cb + 4];
                kr[0] = k0v.x; kr[1] = k0v.y; kr[2] = k0v.z; kr[3] = k0v.w;
                kr[4] = k1v.x; kr[5] = k1v.y; kr[6] = k1v.z; kr[7] = k1v.w;
                float4 q0v = *(float4*)&sq[t][cb];
                float4 q1v = *(float4*)&sq[t][cb + 4];
                qr[0] = q0v.x; qr[1] = q0v.y; qr[2] = q0v.z; qr[3] = q0v.w;
                qr[4] = q1v.x; qr[5] = q1v.y; qr[6] = q1v.z; qr[7] = q1v.w;
            }
            float u0 = 0.f, u1 = 0.f, x0 = 0.f, x1 = 0.f;
#pragma unroll
            for (int i = 0; i < 8; i += 2) {
                u0 = fmaf(S[i],     kr[i],     u0);
                u1 = fmaf(S[i + 1], kr[i + 1], u1);
                x0 = fmaf(S[i],     qr[i],     x0);
                x1 = fmaf(S[i + 1], qr[i + 1], x1);
            }
            float u  = u0 + u1;
            float uq = x0 + x1;
            u  += __shfl_xor_sync(0xFFFFFFFFu, u, 1);
            uq += __shfl_xor_sync(0xFFFFFFFFu, uq, 1);
            u  += __shfl_xor_sync(0xFFFFFFFFu, u, 2);
            uq += __shfl_xor_sync(0xFFFFFFFFu, uq, 2);
            u  += __shfl_xor_sync(0xFFFFFFFFu, u, 4);
            uq += __shfl_xor_sync(0xFFFFFFFFu, uq, 4);

            const float a  = sa[t];
            const float bt = sbv[t];
            const float vv = sv[t][rl];
            const float w  = bt * (vv - a * u);

#pragma unroll
            for (int i = 0; i < 8; i += 2) {
                S[i]     = fmaf(a, S[i],     w * kr[i]);
                S[i + 1] = fmaf(a, S[i + 1], w * kr[i + 1]);
            }
            if (c == 0) {
                float o = fmaf(a, uq, w * sp[t]);
                yout[(size_t)(t0 + t) * Dd + rl] = o;
            }
        }
    }
}

// ---------------------------------------------------------------------------
// Residual depthwise causal conv (proven, fp32 out).
// ---------------------------------------------------------------------------
__global__ __launch_bounds__(256)
void conv_kernel(const float* __restrict__ y, const float* __restrict__ Wc,
                 float* __restrict__ z)
{
    int idx = blockIdx.x * 256 + threadIdx.x;
    int cch = idx & (HDd - 1);
    int l   = (idx >> 10) & (Lseq - 1);
    float4 w = *(const float4*)(Wc + cch * 4);
    float acc = y[idx];
    if (l >= 3) acc = fmaf(w.x, y[idx - 3 * HDd], acc);
    if (l >= 2) acc = fmaf(w.y, y[idx - 2 * HDd], acc);
    if (l >= 1) acc = fmaf(w.z, y[idx - 1 * HDd], acc);
    acc = fmaf(w.w, y[idx], acc);
    z[idx] = acc;
}

// ---------------------------------------------------------------------------
extern "C" void kernel_launch(void* const* d_in, const int* in_sizes, int n_in,
                              void* d_out, int out_size)
{
    const float* hs = (const float*)d_in[0];
    const float* Wq = (const float*)d_in[1];
    const float* bq = (const float*)d_in[2];
    const float* Wk = (const float*)d_in[3];
    const float* bk = (const float*)d_in[4];
    const float* Wv = (const float*)d_in[5];
    const float* bv = (const float*)d_in[6];
    const float* Wa = (const float*)d_in[7];
    const float* Wb = (const float*)d_in[8];
    const float* Wc = (const float*)d_in[9];
    const float* Wo = (const float*)d_in[10];
    const float* bo = (const float*)d_in[11];
    float* out = (float*)d_out;

    float *pq, *pk, *pv, *pa, *pb, *py, *pz, *ps, *pis;
    cudaGetSymbolAddress((void**)&pq, g_q);
    cudaGetSymbolAddress((void**)&pk, g_k);
    cudaGetSymbolAddress((void**)&pv, g_v);
    cudaGetSymbolAddress((void**)&pa, g_alpha);
    cudaGetSymbolAddress((void**)&pb, g_beta);
    cudaGetSymbolAddress((void**)&py, g_y);
    cudaGetSymbolAddress((void**)&pz, g_z);
    cudaGetSymbolAddress((void**)&ps, g_s);
    cudaGetSymbolAddress((void**)&pis, g_is);

    // 1) fused QKV projections (tensor cores, fp16-split)
    dim3 gqkv(8, 16, 3);
    gemm_wmma<<<gqkv, 256>>>(hs, Wq, Wk, Wv, pq, pk, pv);
    dim3 gb(Mtot * 1024 / 256, 1, 3);
    bias_kernel<<<gb, 256>>>(pq, pk, pv, bq, bk, bv);

    // 2) alpha / beta gates
    ab_kernel<<<Mtot / 8, 256>>>(hs, Wa, Wb, pa, pb);

    // 3) sequential gated-delta scan (v4: vectorized smem)
    scan_kernel<<<Bb * NHn * 4, 128>>>(pq, pk, pv, pa, pb, py);

    // 4) residual depthwise causal conv (fp32)
    conv_kernel<<<(Bb * Lseq * HDd) / 256, 256>>>(py, Wc, pz);

    // 5) output projection: per-row dynamic scaling -> fp16-split wmma
    rowmax_kernel<<<Mtot / 8, 256>>>(pz, ps, pis);
    dim3 gout(8, 16, 1);
    gemm_wmma_rs<<<gout, 256>>>(pz, Wo, out, pis);
    bias_scale_kernel<<<Mtot * 1024 / 256, 256>>>(out, ps, bo);
}